// round 7
// baseline (speedup 1.0000x reference)
#include <cuda_runtime.h>
#include <cuda_bf16.h>
#include <float.h>

#define N_NODES 50000
#define N_EDGES 1600000
#define F_HID   240
#define F_OUT   80
#define SCAN_B  256
#define SCAN_G  ((N_NODES + SCAN_B - 1) / SCAN_B)   // 196

// ---------------- scratch (device globals; no allocation allowed) ----------
__device__ float g_deg[N_NODES];
__device__ float g_dis[N_NODES];
__device__ int   g_cnt[N_NODES];
__device__ int   g_off[N_NODES];
__device__ int   g_cur[N_NODES];
__device__ int   g_blksum[SCAN_G];
__device__ int   g_blkoff[SCAN_G];
__device__ int2  g_edge[N_EDGES];                   // (src, nrm bits) packed
__device__ float g_bufA[(size_t)N_NODES * F_HID];   // GEMM outputs (pre-agg)
__device__ float g_bufB[(size_t)N_NODES * F_HID];   // agg outputs (post-relu)

// ---------------- graph preprocessing --------------------------------------
__global__ void zero_kernel() {
    int i = blockIdx.x * blockDim.x + threadIdx.x;
    if (i < N_NODES) { g_deg[i] = 0.0f; g_cnt[i] = 0; }
}

__global__ void deg_kernel(const int* __restrict__ ei,
                           const float* __restrict__ ew) {
    int e = blockIdx.x * blockDim.x + threadIdx.x;
    if (e < N_EDGES) {
        int c = ei[N_EDGES + e];
        if ((unsigned)c < N_NODES) {
            atomicAdd(&g_deg[c], ew[e]);
            atomicAdd(&g_cnt[c], 1);
        }
    }
}

// ---- parallel exclusive scan of g_cnt -> g_off / g_cur (3 phases) ---------
// scan1 also computes g_dis (elementwise, independent).
__global__ void scan1_kernel() {
    __shared__ int s[SCAN_B];
    int t = threadIdx.x;
    int i = blockIdx.x * SCAN_B + t;
    int v = 0;
    if (i < N_NODES) {
        v = g_cnt[i];
        g_dis[i] = rsqrtf(g_deg[i] + 1.0f);  // +1 = self loop
    }
    s[t] = v;
    __syncthreads();
    for (int d = SCAN_B / 2; d > 0; d >>= 1) {
        if (t < d) s[t] += s[t + d];
        __syncthreads();
    }
    if (t == 0) g_blksum[blockIdx.x] = s[0];
}

__global__ void scan2_kernel() {   // 1 block: exclusive scan of 196 block sums
    __shared__ int s[SCAN_B];
    int t = threadIdx.x;
    int v = (t < SCAN_G) ? g_blksum[t] : 0;
    s[t] = v;
    __syncthreads();
    for (int d = 1; d < SCAN_B; d <<= 1) {
        int u = (t >= d) ? s[t - d] : 0;
        __syncthreads();
        s[t] += u;
        __syncthreads();
    }
    if (t < SCAN_G) g_blkoff[t] = s[t] - v;
}

__global__ void scan3_kernel() {   // per-block exclusive scan + block offset
    __shared__ int s[SCAN_B];
    int t = threadIdx.x;
    int i = blockIdx.x * SCAN_B + t;
    int v = (i < N_NODES) ? g_cnt[i] : 0;
    s[t] = v;
    __syncthreads();
    for (int d = 1; d < SCAN_B; d <<= 1) {
        int u = (t >= d) ? s[t - d] : 0;
        __syncthreads();
        s[t] += u;
        __syncthreads();
    }
    if (i < N_NODES) {
        int excl = s[t] - v + g_blkoff[blockIdx.x];
        g_off[i] = excl;
        g_cur[i] = excl;
    }
}

__global__ void fill_kernel(const int* __restrict__ ei,
                            const float* __restrict__ ew) {
    int e = blockIdx.x * blockDim.x + threadIdx.x;
    if (e < N_EDGES) {
        int r = ei[e];
        int c = ei[N_EDGES + e];
        if ((unsigned)r < N_NODES && (unsigned)c < N_NODES) {
            float nrm = g_dis[r] * ew[e] * g_dis[c];
            int p = atomicAdd(&g_cur[c], 1);
            g_edge[p] = make_int2(r, __float_as_int(nrm));
        }
    }
}

// ---------------- GEMM1: [N,5] @ [5,240] -> g_bufA -------------------------
__global__ void gemm1_kernel(const float* __restrict__ x,
                             const float* __restrict__ W1) {
    int idx = blockIdx.x * blockDim.x + threadIdx.x;
    if (idx >= N_NODES * F_HID) return;
    int n = idx / F_HID, f = idx - n * F_HID;
    const float* xr = x + n * 5;
    float acc = 0.0f;
#pragma unroll
    for (int k = 0; k < 5; k++) acc = fmaf(xr[k], W1[k * F_HID + f], acc);
    g_bufA[idx] = acc;
}

// ---------------- scatter-max aggregation (CSR, float4 gathers) -------------
// Reads g_bufA, writes relu(max-agg + bias) to g_bufB.
// 256 threads/node: 4 edge-groups x 64 lanes (60 active, one float4 each).
__global__ void agg_kernel(const float* __restrict__ bias) {
    const float4* __restrict__ h4   = (const float4*)g_bufA;   // stride 60
    float4* __restrict__       out4 = (float4*)g_bufB;
    int n   = blockIdx.x;
    int tid = threadIdx.x;
    int grp = tid >> 6;        // 0..3
    int f4  = tid & 63;        // 0..63, active if < 60

    __shared__ int2   s_e[128];
    __shared__ float4 s_red[4][60];

    float d     = g_dis[n];
    int   start = g_off[n];
    int   cnt   = g_cnt[n];

    float4 v = make_float4(-FLT_MAX, -FLT_MAX, -FLT_MAX, -FLT_MAX);

    for (int base = 0; base < cnt; base += 128) {
        int m = min(128, cnt - base);
        __syncthreads();
        if (tid < m) s_e[tid] = g_edge[start + base + tid];
        __syncthreads();
        if (f4 < 60) {
            for (int e = grp; e < m; e += 4) {
                int2  ed  = s_e[e];
                float nrm = __int_as_float(ed.y);
                float4 hv = h4[(size_t)ed.x * 60 + f4];
                v.x = fmaxf(v.x, nrm * hv.x);
                v.y = fmaxf(v.y, nrm * hv.y);
                v.z = fmaxf(v.z, nrm * hv.z);
                v.w = fmaxf(v.w, nrm * hv.w);
            }
        }
    }
    if (f4 < 60) s_red[grp][f4] = v;
    __syncthreads();

    if (tid < 60) {
        float4 a = s_red[0][tid], b = s_red[1][tid];
        float4 c = s_red[2][tid], e = s_red[3][tid];
        float4 m4;
        m4.x = fmaxf(fmaxf(a.x, b.x), fmaxf(c.x, e.x));
        m4.y = fmaxf(fmaxf(a.y, b.y), fmaxf(c.y, e.y));
        m4.z = fmaxf(fmaxf(a.z, b.z), fmaxf(c.z, e.z));
        m4.w = fmaxf(fmaxf(a.w, b.w), fmaxf(c.w, e.w));
        // self-loop term: dis[n]^2 * h[n]
        float  dd = d * d;
        float4 hv = h4[(size_t)n * 60 + tid];
        m4.x = fmaxf(m4.x, dd * hv.x);
        m4.y = fmaxf(m4.y, dd * hv.y);
        m4.z = fmaxf(m4.z, dd * hv.z);
        m4.w = fmaxf(m4.w, dd * hv.w);
        float4 bi = ((const float4*)bias)[tid];
        m4.x = fmaxf(m4.x + bi.x, 0.0f);
        m4.y = fmaxf(m4.y + bi.y, 0.0f);
        m4.z = fmaxf(m4.z + bi.z, 0.0f);
        m4.w = fmaxf(m4.w + bi.w, 0.0f);
        out4[(size_t)n * 60 + tid] = m4;
    }
}

// ---------------- tiled SGEMM: C[M,Nn] = g_bufB[M,K] @ B[K,Nn] (+bias) -----
// BM=128, BN=80, BK=16, 256 threads, 8x5 micro-tile.
// Software-pipelined: next tile staged in registers during compute.
// As padded to 132 so a-fragment loads are 16B-aligned LDS.128.
template <int DST>  // 0: C = g_bufA ; 1: C = Cout (harness output)
__global__ void gemm_kernel(const float* __restrict__ B,
                            const float* __restrict__ bias,
                            float* __restrict__ Cout,
                            int M, int Nn, int K) {
    const float* __restrict__ A = g_bufB;
    float* __restrict__ C = DST == 0 ? g_bufA : Cout;

    __shared__ float As[16][132];
    __shared__ float Bs[16][80];

    int tid = threadIdx.x;
    int ty = tid / 16, tx = tid % 16;
    int m0 = blockIdx.x * 128;
    int n0 = blockIdx.y * 80;

    float acc[8][5];
#pragma unroll
    for (int i = 0; i < 8; i++)
#pragma unroll
        for (int j = 0; j < 5; j++) acc[i][j] = 0.0f;

    float areg[8], breg[5];

    // prologue: stage tile 0
#pragma unroll
    for (int i = 0; i < 8; i++) {
        int l = tid + i * 256;
        int r = l >> 4, c = l & 15;
        int row = m0 + r;
        row = row < M ? row : M - 1;
        areg[i] = A[(size_t)row * K + c];
    }
#pragma unroll
    for (int i = 0; i < 5; i++) {
        int l = tid + i * 256;
        int r = l / 80, c = l - r * 80;
        breg[i] = B[(size_t)r * Nn + n0 + c];
    }

    int nk = K / 16;
    for (int kt = 0; kt < nk; kt++) {
        // commit staged regs to smem
#pragma unroll
        for (int i = 0; i < 8; i++) {
            int l = tid + i * 256;
            int r = l >> 4, c = l & 15;
            As[c][r] = areg[i];
        }
#pragma unroll
        for (int i = 0; i < 5; i++) {
            int l = tid + i * 256;
            int r = l / 80, c = l - r * 80;
            Bs[r][c] = breg[i];
        }
        __syncthreads();

        // stage next tile while computing this one
        if (kt + 1 < nk) {
            int k0 = (kt + 1) * 16;
#pragma unroll
            for (int i = 0; i < 8; i++) {
                int l = tid + i * 256;
                int r = l >> 4, c = l & 15;
                int row = m0 + r;
                row = row < M ? row : M - 1;
                areg[i] = A[(size_t)row * K + k0 + c];
            }
#pragma unroll
            for (int i = 0; i < 5; i++) {
                int l = tid + i * 256;
                int r = l / 80, c = l - r * 80;
                breg[i] = B[(size_t)(k0 + r) * Nn + n0 + c];
            }
        }

#pragma unroll
        for (int kk = 0; kk < 16; kk++) {
            float4 a0 = *(const float4*)&As[kk][ty * 8];
            float4 a1 = *(const float4*)&As[kk][ty * 8 + 4];
            float b[5];
#pragma unroll
            for (int j = 0; j < 5; j++) b[j] = Bs[kk][tx * 5 + j];
            float a[8] = {a0.x, a0.y, a0.z, a0.w, a1.x, a1.y, a1.z, a1.w};
#pragma unroll
            for (int i = 0; i < 8; i++)
#pragma unroll
                for (int j = 0; j < 5; j++) acc[i][j] = fmaf(a[i], b[j], acc[i][j]);
        }
        __syncthreads();
    }

#pragma unroll
    for (int i = 0; i < 8; i++) {
        int row = m0 + ty * 8 + i;
        if (row < M) {
#pragma unroll
            for (int j = 0; j < 5; j++) {
                int col = n0 + tx * 5 + j;
                float v = acc[i][j];
                if (bias) v += bias[col];
                C[(size_t)row * Nn + col] = v;
            }
        }
    }
}

// ---------------- launch ----------------------------------------------------
// Dataflow:
//   gemm1:  x @ W1                 -> bufA
//   agg :   relu(max-agg(bufA)+b1) -> bufB
//   gemm2:  bufB @ W2              -> bufA
//   agg :   relu(max-agg(bufA)+b2) -> bufB
//   head :  bufB @ We + be         -> out
extern "C" void kernel_launch(void* const* d_in, const int* in_sizes, int n_in,
                              void* d_out, int out_size) {
    const float* x  = (const float*)d_in[0];
    const int*   ei = (const int*)d_in[1];     // int32 (JAX x64 disabled)
    const float* ew = (const float*)d_in[2];
    const float* W1 = (const float*)d_in[3];
    const float* b1 = (const float*)d_in[4];
    const float* W2 = (const float*)d_in[5];
    const float* b2 = (const float*)d_in[6];
    const float* We = (const float*)d_in[7];
    const float* be = (const float*)d_in[8];
    float* out = (float*)d_out;

    const int TB = 256;
    int gN = (N_NODES + TB - 1) / TB;
    int gE = (N_EDGES + TB - 1) / TB;

    // graph structure (shared by both layers)
    zero_kernel<<<gN, TB>>>();
    deg_kernel<<<gE, TB>>>(ei, ew);
    scan1_kernel<<<SCAN_G, SCAN_B>>>();   // also computes g_dis
    scan2_kernel<<<1, SCAN_B>>>();
    scan3_kernel<<<SCAN_G, SCAN_B>>>();
    fill_kernel<<<gE, TB>>>(ei, ew);

    // layer 1
    gemm1_kernel<<<(N_NODES * F_HID + TB - 1) / TB, TB>>>(x, W1);
    agg_kernel<<<N_NODES, TB>>>(b1);

    // layer 2
    {
        dim3 grid((N_NODES + 127) / 128, F_HID / 80);
        gemm_kernel<0><<<grid, 256>>>(W2, nullptr, nullptr, N_NODES, F_HID, F_HID);
    }
    agg_kernel<<<N_NODES, TB>>>(b2);

    // head
    {
        dim3 grid((N_NODES + 127) / 128, F_OUT / 80);
        gemm_kernel<1><<<grid, 256>>>(We, be, out, N_NODES, F_OUT, F_HID);
    }
}

// round 8
// speedup vs baseline: 1.0835x; 1.0835x over previous
#include <cuda_runtime.h>
#include <cuda_fp16.h>
#include <float.h>

#define N_NODES 50000
#define N_EDGES 1600000
#define F_HID   240
#define F_OUT   80
#define SCAN_B  256
#define SCAN_G  ((N_NODES + SCAN_B - 1) / SCAN_B)   // 196

// ---------------- scratch (device globals; no allocation allowed) ----------
__device__ float  g_deg[N_NODES];
__device__ float  g_dis[N_NODES];
__device__ int    g_cnt[N_NODES];
__device__ int    g_off[N_NODES];
__device__ int    g_cur[N_NODES];
__device__ int    g_blksum[SCAN_G];
__device__ int    g_blkoff[SCAN_G];
__device__ int2   g_edge[N_EDGES];                    // (src, nrm bits)
__device__ __half g_bufH[(size_t)N_NODES * F_HID];    // pre-agg features, fp16
__device__ float  g_bufB[(size_t)N_NODES * F_HID];    // agg outputs, fp32

// ---------------- graph preprocessing --------------------------------------
__global__ void zero_kernel() {
    int i = blockIdx.x * blockDim.x + threadIdx.x;
    if (i < N_NODES) { g_deg[i] = 0.0f; g_cnt[i] = 0; }
}

__global__ void deg_kernel(const int* __restrict__ ei,
                           const float* __restrict__ ew) {
    int e = blockIdx.x * blockDim.x + threadIdx.x;
    if (e < N_EDGES) {
        int c = ei[N_EDGES + e];
        if ((unsigned)c < N_NODES) {
            atomicAdd(&g_deg[c], ew[e]);
            atomicAdd(&g_cnt[c], 1);
        }
    }
}

// ---- parallel exclusive scan of g_cnt -> g_off / g_cur (3 phases) ---------
__global__ void scan1_kernel() {
    __shared__ int s[SCAN_B];
    int t = threadIdx.x;
    int i = blockIdx.x * SCAN_B + t;
    int v = 0;
    if (i < N_NODES) {
        v = g_cnt[i];
        g_dis[i] = rsqrtf(g_deg[i] + 1.0f);  // +1 = self loop
    }
    s[t] = v;
    __syncthreads();
    for (int d = SCAN_B / 2; d > 0; d >>= 1) {
        if (t < d) s[t] += s[t + d];
        __syncthreads();
    }
    if (t == 0) g_blksum[blockIdx.x] = s[0];
}

__global__ void scan2_kernel() {
    __shared__ int s[SCAN_B];
    int t = threadIdx.x;
    int v = (t < SCAN_G) ? g_blksum[t] : 0;
    s[t] = v;
    __syncthreads();
    for (int d = 1; d < SCAN_B; d <<= 1) {
        int u = (t >= d) ? s[t - d] : 0;
        __syncthreads();
        s[t] += u;
        __syncthreads();
    }
    if (t < SCAN_G) g_blkoff[t] = s[t] - v;
}

__global__ void scan3_kernel() {
    __shared__ int s[SCAN_B];
    int t = threadIdx.x;
    int i = blockIdx.x * SCAN_B + t;
    int v = (i < N_NODES) ? g_cnt[i] : 0;
    s[t] = v;
    __syncthreads();
    for (int d = 1; d < SCAN_B; d <<= 1) {
        int u = (t >= d) ? s[t - d] : 0;
        __syncthreads();
        s[t] += u;
        __syncthreads();
    }
    if (i < N_NODES) {
        int excl = s[t] - v + g_blkoff[blockIdx.x];
        g_off[i] = excl;
        g_cur[i] = excl;
    }
}

__global__ void fill_kernel(const int* __restrict__ ei,
                            const float* __restrict__ ew) {
    int e = blockIdx.x * blockDim.x + threadIdx.x;
    if (e < N_EDGES) {
        int r = ei[e];
        int c = ei[N_EDGES + e];
        if ((unsigned)r < N_NODES && (unsigned)c < N_NODES) {
            float nrm = g_dis[r] * ew[e] * g_dis[c];
            int p = atomicAdd(&g_cur[c], 1);
            g_edge[p] = make_int2(r, __float_as_int(nrm));
        }
    }
}

// ---------------- GEMM1: [N,5] @ [5,240] -> g_bufH (fp16) ------------------
// one thread per 4 consecutive output features, vectorized uint2 store.
__global__ void gemm1_kernel(const float* __restrict__ x,
                             const float* __restrict__ W1) {
    int idx = blockIdx.x * blockDim.x + threadIdx.x;   // [0, N*60)
    if (idx >= N_NODES * 60) return;
    int n = idx / 60, q = idx - n * 60;                // features q*4..q*4+3
    const float* xr = x + n * 5;
    float a0 = 0, a1 = 0, a2 = 0, a3 = 0;
#pragma unroll
    for (int k = 0; k < 5; k++) {
        float xv = xr[k];
        const float* w = W1 + k * F_HID + q * 4;
        a0 = fmaf(xv, w[0], a0);
        a1 = fmaf(xv, w[1], a1);
        a2 = fmaf(xv, w[2], a2);
        a3 = fmaf(xv, w[3], a3);
    }
    __half2 p0 = __floats2half2_rn(a0, a1);
    __half2 p1 = __floats2half2_rn(a2, a3);
    uint2 u;
    u.x = *(unsigned*)&p0;
    u.y = *(unsigned*)&p1;
    ((uint2*)g_bufH)[idx] = u;
}

// ---------------- scatter-max aggregation (CSR, fp16 gathers) ---------------
// Reads g_bufH (fp16), computes in fp32, writes relu(max+bias) to g_bufB.
// 256 threads/node: 8 edge-groups x 32 lanes (30 active, uint4 = 8 halves).
__global__ void agg_kernel(const float* __restrict__ bias) {
    const uint4* __restrict__ hp   = (const uint4*)g_bufH;   // 30 uint4 / row
    float4* __restrict__      out4 = (float4*)g_bufB;        // 60 float4 / row
    int n   = blockIdx.x;
    int tid = threadIdx.x;
    int grp = tid >> 5;        // 0..7
    int f   = tid & 31;        // active if < 30 (covers 8 halves each)

    __shared__ int2   s_e[128];
    __shared__ float4 s_red[8][30][2];

    float d     = g_dis[n];
    int   start = g_off[n];
    int   cnt   = g_cnt[n];

    float4 vlo = make_float4(-FLT_MAX, -FLT_MAX, -FLT_MAX, -FLT_MAX);
    float4 vhi = vlo;

    for (int base = 0; base < cnt; base += 128) {
        int m = min(128, cnt - base);
        __syncthreads();
        if (tid < m) s_e[tid] = g_edge[start + base + tid];
        __syncthreads();
        if (f < 30) {
            for (int e = grp; e < m; e += 8) {
                int2   ed  = s_e[e];
                float  nrm = __int_as_float(ed.y);
                uint4  hv  = hp[(size_t)ed.x * 30 + f];
                float2 q0 = __half22float2(*(const __half2*)&hv.x);
                float2 q1 = __half22float2(*(const __half2*)&hv.y);
                float2 q2 = __half22float2(*(const __half2*)&hv.z);
                float2 q3 = __half22float2(*(const __half2*)&hv.w);
                vlo.x = fmaxf(vlo.x, nrm * q0.x);
                vlo.y = fmaxf(vlo.y, nrm * q0.y);
                vlo.z = fmaxf(vlo.z, nrm * q1.x);
                vlo.w = fmaxf(vlo.w, nrm * q1.y);
                vhi.x = fmaxf(vhi.x, nrm * q2.x);
                vhi.y = fmaxf(vhi.y, nrm * q2.y);
                vhi.z = fmaxf(vhi.z, nrm * q3.x);
                vhi.w = fmaxf(vhi.w, nrm * q3.y);
            }
        }
    }
    if (f < 30) { s_red[grp][f][0] = vlo; s_red[grp][f][1] = vhi; }
    __syncthreads();

    if (tid < 60) {            // float4 index tid -> lane f=tid/2, part=tid&1
        int fl = tid >> 1, pt = tid & 1;
        float4 m4 = s_red[0][fl][pt];
#pragma unroll
        for (int g = 1; g < 8; g++) {
            float4 r = s_red[g][fl][pt];
            m4.x = fmaxf(m4.x, r.x);
            m4.y = fmaxf(m4.y, r.y);
            m4.z = fmaxf(m4.z, r.z);
            m4.w = fmaxf(m4.w, r.w);
        }
        // self-loop term: dis[n]^2 * h[n] (fp16 source)
        float  dd = d * d;
        uint2  sv = ((const uint2*)g_bufH)[(size_t)n * 60 + tid];
        float2 s0 = __half22float2(*(const __half2*)&sv.x);
        float2 s1 = __half22float2(*(const __half2*)&sv.y);
        m4.x = fmaxf(m4.x, dd * s0.x);
        m4.y = fmaxf(m4.y, dd * s0.y);
        m4.z = fmaxf(m4.z, dd * s1.x);
        m4.w = fmaxf(m4.w, dd * s1.y);
        float4 bi = ((const float4*)bias)[tid];
        m4.x = fmaxf(m4.x + bi.x, 0.0f);
        m4.y = fmaxf(m4.y + bi.y, 0.0f);
        m4.z = fmaxf(m4.z + bi.z, 0.0f);
        m4.w = fmaxf(m4.w + bi.w, 0.0f);
        out4[(size_t)n * 60 + tid] = m4;
    }
}

// ---------------- tiled SGEMM: C[M,Nn] = g_bufB[M,K] @ B[K,Nn] (+bias) -----
// R5-measured form: BM=128, BN=80, BK=16, 256 threads, 8x5 micro-tile.
// DST=0: write fp16 to g_bufH (pre-agg). DST=1: write fp32 to Cout (+bias).
template <int DST>
__global__ void __launch_bounds__(256, 2)
gemm_kernel(const float* __restrict__ B,
            const float* __restrict__ bias,
            float* __restrict__ Cout,
            int M, int Nn, int K) {
    const float* __restrict__ A = g_bufB;

    __shared__ float As[16][129];
    __shared__ float Bs[16][80];

    int tid = threadIdx.x;
    int ty = tid / 16, tx = tid % 16;
    int m0 = blockIdx.x * 128;
    int n0 = blockIdx.y * 80;

    float acc[8][5];
#pragma unroll
    for (int i = 0; i < 8; i++)
#pragma unroll
        for (int j = 0; j < 5; j++) acc[i][j] = 0.0f;

    for (int k0 = 0; k0 < K; k0 += 16) {
#pragma unroll
        for (int i = 0; i < 8; i++) {
            int l = tid + i * 256;
            int r = l >> 4, c = l & 15;
            int row = m0 + r;
            row = row < M ? row : M - 1;
            As[c][r] = A[(size_t)row * K + k0 + c];
        }
#pragma unroll
        for (int i = 0; i < 5; i++) {
            int l = tid + i * 256;
            int r = l / 80, c = l - r * 80;
            Bs[r][c] = B[(size_t)(k0 + r) * Nn + n0 + c];
        }
        __syncthreads();
#pragma unroll
        for (int kk = 0; kk < 16; kk++) {
            float a[8], b[5];
#pragma unroll
            for (int i = 0; i < 8; i++) a[i] = As[kk][ty * 8 + i];
#pragma unroll
            for (int j = 0; j < 5; j++) b[j] = Bs[kk][tx * 5 + j];
#pragma unroll
            for (int i = 0; i < 8; i++)
#pragma unroll
                for (int j = 0; j < 5; j++) acc[i][j] = fmaf(a[i], b[j], acc[i][j]);
        }
        __syncthreads();
    }

#pragma unroll
    for (int i = 0; i < 8; i++) {
        int row = m0 + ty * 8 + i;
        if (row < M) {
#pragma unroll
            for (int j = 0; j < 5; j++) {
                int col = n0 + tx * 5 + j;
                if (DST == 0) {
                    g_bufH[(size_t)row * F_HID + col] = __float2half_rn(acc[i][j]);
                } else {
                    Cout[(size_t)row * Nn + col] = acc[i][j] + bias[col];
                }
            }
        }
    }
}

// ---------------- launch ----------------------------------------------------
// Dataflow:
//   gemm1:  x @ W1                  -> bufH (fp16)
//   agg :   relu(max-agg(bufH)+b1)  -> bufB (fp32)
//   gemm2:  bufB @ W2               -> bufH (fp16)
//   agg :   relu(max-agg(bufH)+b2)  -> bufB (fp32)
//   head :  bufB @ We + be          -> out  (fp32)
extern "C" void kernel_launch(void* const* d_in, const int* in_sizes, int n_in,
                              void* d_out, int out_size) {
    const float* x  = (const float*)d_in[0];
    const int*   ei = (const int*)d_in[1];     // int32 (JAX x64 disabled)
    const float* ew = (const float*)d_in[2];
    const float* W1 = (const float*)d_in[3];
    const float* b1 = (const float*)d_in[4];
    const float* W2 = (const float*)d_in[5];
    const float* b2 = (const float*)d_in[6];
    const float* We = (const float*)d_in[7];
    const float* be = (const float*)d_in[8];
    float* out = (float*)d_out;

    const int TB = 256;
    int gN = (N_NODES + TB - 1) / TB;
    int gE = (N_EDGES + TB - 1) / TB;

    // graph structure (shared by both layers)
    zero_kernel<<<gN, TB>>>();
    deg_kernel<<<gE, TB>>>(ei, ew);
    scan1_kernel<<<SCAN_G, SCAN_B>>>();   // also computes g_dis
    scan2_kernel<<<1, SCAN_B>>>();
    scan3_kernel<<<SCAN_G, SCAN_B>>>();
    fill_kernel<<<gE, TB>>>(ei, ew);

    // layer 1
    gemm1_kernel<<<(N_NODES * 60 + TB - 1) / TB, TB>>>(x, W1);
    agg_kernel<<<N_NODES, TB>>>(b1);

    // layer 2
    {
        dim3 grid((N_NODES + 127) / 128, F_HID / 80);
        gemm_kernel<0><<<grid, 256>>>(W2, nullptr, nullptr, N_NODES, F_HID, F_HID);
    }
    agg_kernel<<<N_NODES, TB>>>(b2);

    // head
    {
        dim3 grid((N_NODES + 127) / 128, F_OUT / 80);
        gemm_kernel<1><<<grid, 256>>>(We, be, out, N_NODES, F_OUT, F_HID);
    }
}

// round 9
// speedup vs baseline: 1.4454x; 1.3341x over previous
#include <cuda_runtime.h>
#include <cuda_fp16.h>
#include <float.h>

#define N_NODES 50000
#define N_EDGES 1600000
#define F_HID   240
#define F_OUT   80
#define SCAN_B  256
#define SCAN_G  ((N_NODES + SCAN_B - 1) / SCAN_B)   // 196

// ---------------- scratch (device globals; no allocation allowed) ----------
__device__ float  g_deg[N_NODES];
__device__ float  g_dis[N_NODES];
__device__ int    g_cnt[N_NODES];
__device__ int    g_off[N_NODES];
__device__ int    g_cur[N_NODES];
__device__ int    g_blksum[SCAN_G];
__device__ int    g_blkoff[SCAN_G];
__device__ int2   g_edge[N_EDGES];                    // (src, nrm bits)
__device__ __half g_bufH[(size_t)N_NODES * F_HID];    // pre-agg features, fp16
__device__ float  g_bufB[(size_t)N_NODES * F_HID];    // agg outputs, fp32

// ---------------- graph preprocessing --------------------------------------
__global__ void zero_kernel() {
    int i = blockIdx.x * blockDim.x + threadIdx.x;
    if (i < N_NODES) { g_deg[i] = 0.0f; g_cnt[i] = 0; }
}

__global__ void deg_kernel(const int* __restrict__ ei,
                           const float* __restrict__ ew) {
    int e = blockIdx.x * blockDim.x + threadIdx.x;
    if (e < N_EDGES) {
        int c = ei[N_EDGES + e];
        if ((unsigned)c < N_NODES) {
            atomicAdd(&g_deg[c], ew[e]);
            atomicAdd(&g_cnt[c], 1);
        }
    }
}

// ---- parallel exclusive scan of g_cnt -> g_off / g_cur (3 phases) ---------
__global__ void scan1_kernel() {
    __shared__ int s[SCAN_B];
    int t = threadIdx.x;
    int i = blockIdx.x * SCAN_B + t;
    int v = 0;
    if (i < N_NODES) {
        v = g_cnt[i];
        g_dis[i] = rsqrtf(g_deg[i] + 1.0f);  // +1 = self loop
    }
    s[t] = v;
    __syncthreads();
    for (int d = SCAN_B / 2; d > 0; d >>= 1) {
        if (t < d) s[t] += s[t + d];
        __syncthreads();
    }
    if (t == 0) g_blksum[blockIdx.x] = s[0];
}

__global__ void scan2_kernel() {
    __shared__ int s[SCAN_B];
    int t = threadIdx.x;
    int v = (t < SCAN_G) ? g_blksum[t] : 0;
    s[t] = v;
    __syncthreads();
    for (int d = 1; d < SCAN_B; d <<= 1) {
        int u = (t >= d) ? s[t - d] : 0;
        __syncthreads();
        s[t] += u;
        __syncthreads();
    }
    if (t < SCAN_G) g_blkoff[t] = s[t] - v;
}

__global__ void scan3_kernel() {
    __shared__ int s[SCAN_B];
    int t = threadIdx.x;
    int i = blockIdx.x * SCAN_B + t;
    int v = (i < N_NODES) ? g_cnt[i] : 0;
    s[t] = v;
    __syncthreads();
    for (int d = 1; d < SCAN_B; d <<= 1) {
        int u = (t >= d) ? s[t - d] : 0;
        __syncthreads();
        s[t] += u;
        __syncthreads();
    }
    if (i < N_NODES) {
        int excl = s[t] - v + g_blkoff[blockIdx.x];
        g_off[i] = excl;
        g_cur[i] = excl;
    }
}

__global__ void fill_kernel(const int* __restrict__ ei,
                            const float* __restrict__ ew) {
    int e = blockIdx.x * blockDim.x + threadIdx.x;
    if (e < N_EDGES) {
        int r = ei[e];
        int c = ei[N_EDGES + e];
        if ((unsigned)r < N_NODES && (unsigned)c < N_NODES) {
            float nrm = g_dis[r] * ew[e] * g_dis[c];
            int p = atomicAdd(&g_cur[c], 1);
            g_edge[p] = make_int2(r, __float_as_int(nrm));
        }
    }
}

// ---------------- GEMM1: [N,5] @ [5,240] -> g_bufH (fp16) ------------------
__global__ void gemm1_kernel(const float* __restrict__ x,
                             const float* __restrict__ W1) {
    int idx = blockIdx.x * blockDim.x + threadIdx.x;   // [0, N*60)
    if (idx >= N_NODES * 60) return;
    int n = idx / 60, q = idx - n * 60;                // features q*4..q*4+3
    const float* xr = x + n * 5;
    float a0 = 0, a1 = 0, a2 = 0, a3 = 0;
#pragma unroll
    for (int k = 0; k < 5; k++) {
        float xv = xr[k];
        const float* w = W1 + k * F_HID + q * 4;
        a0 = fmaf(xv, w[0], a0);
        a1 = fmaf(xv, w[1], a1);
        a2 = fmaf(xv, w[2], a2);
        a3 = fmaf(xv, w[3], a3);
    }
    __half2 p0 = __floats2half2_rn(a0, a1);
    __half2 p1 = __floats2half2_rn(a2, a3);
    uint2 u;
    u.x = *(unsigned*)&p0;
    u.y = *(unsigned*)&p1;
    ((uint2*)g_bufH)[idx] = u;
}

// ---------------- scatter-max aggregation: WARP PER NODE --------------------
// Lane f (f<30) owns 8 fp16 features (one uint4). Serial edge loop per warp:
// broadcast edge meta (uniform L1-hit load) + one independent gather LDG.128
// per lane per edge; unroll-4 for MLP. No block syncs, no smem reduction.
__global__ void __launch_bounds__(256, 8)
agg_kernel(const float* __restrict__ bias) {
    const uint4* __restrict__ hp   = (const uint4*)g_bufH;   // 30 uint4 / row
    float4* __restrict__      out4 = (float4*)g_bufB;        // 60 float4 / row

    int warp = threadIdx.x >> 5;
    int lane = threadIdx.x & 31;
    int n = blockIdx.x * 8 + warp;
    if (n >= N_NODES) return;
    int f = lane < 30 ? lane : 29;   // lanes 30/31 duplicate lane 29 (discarded)

    int   start = g_off[n];
    int   cnt   = g_cnt[n];
    float d     = g_dis[n];

    float4 vlo = make_float4(-FLT_MAX, -FLT_MAX, -FLT_MAX, -FLT_MAX);
    float4 vhi = vlo;

    const int2* __restrict__ ep = g_edge + start;
#pragma unroll 4
    for (int e = 0; e < cnt; e++) {
        int2   ed  = __ldg(&ep[e]);               // warp-uniform broadcast
        float  nrm = __int_as_float(ed.y);
        uint4  hv  = hp[(size_t)ed.x * 30 + f];   // 16B gather
        float2 q0 = __half22float2(*(const __half2*)&hv.x);
        float2 q1 = __half22float2(*(const __half2*)&hv.y);
        float2 q2 = __half22float2(*(const __half2*)&hv.z);
        float2 q3 = __half22float2(*(const __half2*)&hv.w);
        vlo.x = fmaxf(vlo.x, nrm * q0.x);
        vlo.y = fmaxf(vlo.y, nrm * q0.y);
        vlo.z = fmaxf(vlo.z, nrm * q1.x);
        vlo.w = fmaxf(vlo.w, nrm * q1.y);
        vhi.x = fmaxf(vhi.x, nrm * q2.x);
        vhi.y = fmaxf(vhi.y, nrm * q2.y);
        vhi.z = fmaxf(vhi.z, nrm * q3.x);
        vhi.w = fmaxf(vhi.w, nrm * q3.y);
    }

    // self-loop term: dis[n]^2 * h[n]
    {
        float  dd = d * d;
        uint4  hv = hp[(size_t)n * 30 + f];
        float2 q0 = __half22float2(*(const __half2*)&hv.x);
        float2 q1 = __half22float2(*(const __half2*)&hv.y);
        float2 q2 = __half22float2(*(const __half2*)&hv.z);
        float2 q3 = __half22float2(*(const __half2*)&hv.w);
        vlo.x = fmaxf(vlo.x, dd * q0.x);
        vlo.y = fmaxf(vlo.y, dd * q0.y);
        vlo.z = fmaxf(vlo.z, dd * q1.x);
        vlo.w = fmaxf(vlo.w, dd * q1.y);
        vhi.x = fmaxf(vhi.x, dd * q2.x);
        vhi.y = fmaxf(vhi.y, dd * q2.y);
        vhi.z = fmaxf(vhi.z, dd * q3.x);
        vhi.w = fmaxf(vhi.w, dd * q3.y);
    }

    if (lane < 30) {
        float4 b0 = ((const float4*)bias)[f * 2];
        float4 b1 = ((const float4*)bias)[f * 2 + 1];
        vlo.x = fmaxf(vlo.x + b0.x, 0.0f);
        vlo.y = fmaxf(vlo.y + b0.y, 0.0f);
        vlo.z = fmaxf(vlo.z + b0.z, 0.0f);
        vlo.w = fmaxf(vlo.w + b0.w, 0.0f);
        vhi.x = fmaxf(vhi.x + b1.x, 0.0f);
        vhi.y = fmaxf(vhi.y + b1.y, 0.0f);
        vhi.z = fmaxf(vhi.z + b1.z, 0.0f);
        vhi.w = fmaxf(vhi.w + b1.w, 0.0f);
        out4[(size_t)n * 60 + f * 2]     = vlo;
        out4[(size_t)n * 60 + f * 2 + 1] = vhi;
    }
}

// ---------------- tiled SGEMM: C[M,Nn] = g_bufB[M,K] @ B[K,Nn] (+bias) -----
// R5-measured form: BM=128, BN=80, BK=16, 256 threads, 8x5 micro-tile.
// DST=0: write fp16 to g_bufH (pre-agg). DST=1: write fp32 to Cout (+bias).
template <int DST>
__global__ void __launch_bounds__(256, 2)
gemm_kernel(const float* __restrict__ B,
            const float* __restrict__ bias,
            float* __restrict__ Cout,
            int M, int Nn, int K) {
    const float* __restrict__ A = g_bufB;

    __shared__ float As[16][129];
    __shared__ float Bs[16][80];

    int tid = threadIdx.x;
    int ty = tid / 16, tx = tid % 16;
    int m0 = blockIdx.x * 128;
    int n0 = blockIdx.y * 80;

    float acc[8][5];
#pragma unroll
    for (int i = 0; i < 8; i++)
#pragma unroll
        for (int j = 0; j < 5; j++) acc[i][j] = 0.0f;

    for (int k0 = 0; k0 < K; k0 += 16) {
#pragma unroll
        for (int i = 0; i < 8; i++) {
            int l = tid + i * 256;
            int r = l >> 4, c = l & 15;
            int row = m0 + r;
            row = row < M ? row : M - 1;
            As[c][r] = A[(size_t)row * K + k0 + c];
        }
#pragma unroll
        for (int i = 0; i < 5; i++) {
            int l = tid + i * 256;
            int r = l / 80, c = l - r * 80;
            Bs[r][c] = B[(size_t)(k0 + r) * Nn + n0 + c];
        }
        __syncthreads();
#pragma unroll
        for (int kk = 0; kk < 16; kk++) {
            float a[8], b[5];
#pragma unroll
            for (int i = 0; i < 8; i++) a[i] = As[kk][ty * 8 + i];
#pragma unroll
            for (int j = 0; j < 5; j++) b[j] = Bs[kk][tx * 5 + j];
#pragma unroll
            for (int i = 0; i < 8; i++)
#pragma unroll
                for (int j = 0; j < 5; j++) acc[i][j] = fmaf(a[i], b[j], acc[i][j]);
        }
        __syncthreads();
    }

#pragma unroll
    for (int i = 0; i < 8; i++) {
        int row = m0 + ty * 8 + i;
        if (row < M) {
#pragma unroll
            for (int j = 0; j < 5; j++) {
                int col = n0 + tx * 5 + j;
                if (DST == 0) {
                    g_bufH[(size_t)row * F_HID + col] = __float2half_rn(acc[i][j]);
                } else {
                    Cout[(size_t)row * Nn + col] = acc[i][j] + bias[col];
                }
            }
        }
    }
}

// ---------------- launch ----------------------------------------------------
// Dataflow:
//   gemm1:  x @ W1                  -> bufH (fp16)
//   agg :   relu(max-agg(bufH)+b1)  -> bufB (fp32)
//   gemm2:  bufB @ W2               -> bufH (fp16)
//   agg :   relu(max-agg(bufH)+b2)  -> bufB (fp32)
//   head :  bufB @ We + be          -> out  (fp32)
extern "C" void kernel_launch(void* const* d_in, const int* in_sizes, int n_in,
                              void* d_out, int out_size) {
    const float* x  = (const float*)d_in[0];
    const int*   ei = (const int*)d_in[1];     // int32 (JAX x64 disabled)
    const float* ew = (const float*)d_in[2];
    const float* W1 = (const float*)d_in[3];
    const float* b1 = (const float*)d_in[4];
    const float* W2 = (const float*)d_in[5];
    const float* b2 = (const float*)d_in[6];
    const float* We = (const float*)d_in[7];
    const float* be = (const float*)d_in[8];
    float* out = (float*)d_out;

    const int TB = 256;
    int gN = (N_NODES + TB - 1) / TB;
    int gE = (N_EDGES + TB - 1) / TB;

    // graph structure (shared by both layers)
    zero_kernel<<<gN, TB>>>();
    deg_kernel<<<gE, TB>>>(ei, ew);
    scan1_kernel<<<SCAN_G, SCAN_B>>>();   // also computes g_dis
    scan2_kernel<<<1, SCAN_B>>>();
    scan3_kernel<<<SCAN_G, SCAN_B>>>();
    fill_kernel<<<gE, TB>>>(ei, ew);

    // layer 1
    gemm1_kernel<<<(N_NODES * 60 + TB - 1) / TB, TB>>>(x, W1);
    agg_kernel<<<(N_NODES + 7) / 8, 256>>>(b1);

    // layer 2
    {
        dim3 grid((N_NODES + 127) / 128, F_HID / 80);
        gemm_kernel<0><<<grid, 256>>>(W2, nullptr, nullptr, N_NODES, F_HID, F_HID);
    }
    agg_kernel<<<(N_NODES + 7) / 8, 256>>>(b2);

    // head
    {
        dim3 grid((N_NODES + 127) / 128, F_OUT / 80);
        gemm_kernel<1><<<grid, 256>>>(We, be, out, N_NODES, F_OUT, F_HID);
    }
}

// round 10
// speedup vs baseline: 1.9235x; 1.3307x over previous
#include <cuda_runtime.h>
#include <cuda_fp16.h>
#include <float.h>

#define N_NODES 50000
#define N_EDGES 1600000
#define F_HID   240
#define F_OUT   80
#define SCAN_B  256
#define SCAN_G  ((N_NODES + SCAN_B - 1) / SCAN_B)   // 196

// ---------------- scratch (device globals; no allocation allowed) ----------
__device__ float  g_deg[N_NODES];
__device__ float  g_dis[N_NODES];
__device__ int    g_cnt[N_NODES];
__device__ int    g_off[N_NODES];
__device__ int    g_cur[N_NODES];
__device__ int    g_blksum[SCAN_G];
__device__ int    g_blkoff[SCAN_G];
__device__ int2   g_edge[N_EDGES];                    // (src, nrm bits)
__device__ __half g_bufH[(size_t)N_NODES * F_HID];    // pre-agg features, fp16
__device__ float  g_bufB[(size_t)N_NODES * F_HID];    // agg outputs, fp32
__device__ __half g_aggH[(size_t)N_NODES * F_HID];    // agg outputs, fp16 (mma A)
__device__ __half g_W2h[F_HID * F_HID];               // W2 in fp16

// ---------------- graph preprocessing --------------------------------------
__global__ void zero_kernel() {
    int i = blockIdx.x * blockDim.x + threadIdx.x;
    if (i < N_NODES) { g_deg[i] = 0.0f; g_cnt[i] = 0; }
}

__global__ void deg_kernel(const int* __restrict__ ei,
                           const float* __restrict__ ew) {
    int e = blockIdx.x * blockDim.x + threadIdx.x;
    if (e < N_EDGES) {
        int c = ei[N_EDGES + e];
        if ((unsigned)c < N_NODES) {
            atomicAdd(&g_deg[c], ew[e]);
            atomicAdd(&g_cnt[c], 1);
        }
    }
}

// ---- parallel exclusive scan of g_cnt -> g_off / g_cur (3 phases) ---------
__global__ void scan1_kernel() {
    __shared__ int s[SCAN_B];
    int t = threadIdx.x;
    int i = blockIdx.x * SCAN_B + t;
    int v = 0;
    if (i < N_NODES) {
        v = g_cnt[i];
        g_dis[i] = rsqrtf(g_deg[i] + 1.0f);  // +1 = self loop
    }
    s[t] = v;
    __syncthreads();
    for (int d = SCAN_B / 2; d > 0; d >>= 1) {
        if (t < d) s[t] += s[t + d];
        __syncthreads();
    }
    if (t == 0) g_blksum[blockIdx.x] = s[0];
}

__global__ void scan2_kernel() {
    __shared__ int s[SCAN_B];
    int t = threadIdx.x;
    int v = (t < SCAN_G) ? g_blksum[t] : 0;
    s[t] = v;
    __syncthreads();
    for (int d = 1; d < SCAN_B; d <<= 1) {
        int u = (t >= d) ? s[t - d] : 0;
        __syncthreads();
        s[t] += u;
        __syncthreads();
    }
    if (t < SCAN_G) g_blkoff[t] = s[t] - v;
}

__global__ void scan3_kernel() {
    __shared__ int s[SCAN_B];
    int t = threadIdx.x;
    int i = blockIdx.x * SCAN_B + t;
    int v = (i < N_NODES) ? g_cnt[i] : 0;
    s[t] = v;
    __syncthreads();
    for (int d = 1; d < SCAN_B; d <<= 1) {
        int u = (t >= d) ? s[t - d] : 0;
        __syncthreads();
        s[t] += u;
        __syncthreads();
    }
    if (i < N_NODES) {
        int excl = s[t] - v + g_blkoff[blockIdx.x];
        g_off[i] = excl;
        g_cur[i] = excl;
    }
}

__global__ void fill_kernel(const int* __restrict__ ei,
                            const float* __restrict__ ew) {
    int e = blockIdx.x * blockDim.x + threadIdx.x;
    if (e < N_EDGES) {
        int r = ei[e];
        int c = ei[N_EDGES + e];
        if ((unsigned)r < N_NODES && (unsigned)c < N_NODES) {
            float nrm = g_dis[r] * ew[e] * g_dis[c];
            int p = atomicAdd(&g_cur[c], 1);
            g_edge[p] = make_int2(r, __float_as_int(nrm));
        }
    }
}

// ---------------- W2 -> fp16 (once per launch) ------------------------------
__global__ void cvtW2_kernel(const float* __restrict__ W2) {
    int i = blockIdx.x * blockDim.x + threadIdx.x;   // [0, 240*240/4)
    if (i >= F_HID * F_HID / 4) return;
    float4 v = ((const float4*)W2)[i];
    __half2 p0 = __floats2half2_rn(v.x, v.y);
    __half2 p1 = __floats2half2_rn(v.z, v.w);
    uint2 u;
    u.x = *(unsigned*)&p0;
    u.y = *(unsigned*)&p1;
    ((uint2*)g_W2h)[i] = u;
}

// ---------------- GEMM1: [N,5] @ [5,240] -> g_bufH (fp16) ------------------
__global__ void gemm1_kernel(const float* __restrict__ x,
                             const float* __restrict__ W1) {
    int idx = blockIdx.x * blockDim.x + threadIdx.x;   // [0, N*60)
    if (idx >= N_NODES * 60) return;
    int n = idx / 60, q = idx - n * 60;                // features q*4..q*4+3
    const float* xr = x + n * 5;
    float a0 = 0, a1 = 0, a2 = 0, a3 = 0;
#pragma unroll
    for (int k = 0; k < 5; k++) {
        float xv = xr[k];
        const float* w = W1 + k * F_HID + q * 4;
        a0 = fmaf(xv, w[0], a0);
        a1 = fmaf(xv, w[1], a1);
        a2 = fmaf(xv, w[2], a2);
        a3 = fmaf(xv, w[3], a3);
    }
    __half2 p0 = __floats2half2_rn(a0, a1);
    __half2 p1 = __floats2half2_rn(a2, a3);
    uint2 u;
    u.x = *(unsigned*)&p0;
    u.y = *(unsigned*)&p1;
    ((uint2*)g_bufH)[idx] = u;
}

// ---------------- scatter-max aggregation: WARP PER NODE --------------------
__global__ void __launch_bounds__(256, 8)
agg_kernel(const float* __restrict__ bias) {
    const uint4* __restrict__ hp   = (const uint4*)g_bufH;   // 30 uint4 / row
    float4* __restrict__      out4 = (float4*)g_bufB;        // 60 float4 / row
    uint4* __restrict__       outh = (uint4*)g_aggH;         // 30 uint4 / row

    int warp = threadIdx.x >> 5;
    int lane = threadIdx.x & 31;
    int n = blockIdx.x * 8 + warp;
    if (n >= N_NODES) return;
    int f = lane < 30 ? lane : 29;

    int   start = g_off[n];
    int   cnt   = g_cnt[n];
    float d     = g_dis[n];

    float4 vlo = make_float4(-FLT_MAX, -FLT_MAX, -FLT_MAX, -FLT_MAX);
    float4 vhi = vlo;

    const int2* __restrict__ ep = g_edge + start;
#pragma unroll 4
    for (int e = 0; e < cnt; e++) {
        int2   ed  = __ldg(&ep[e]);
        float  nrm = __int_as_float(ed.y);
        uint4  hv  = hp[(size_t)ed.x * 30 + f];
        float2 q0 = __half22float2(*(const __half2*)&hv.x);
        float2 q1 = __half22float2(*(const __half2*)&hv.y);
        float2 q2 = __half22float2(*(const __half2*)&hv.z);
        float2 q3 = __half22float2(*(const __half2*)&hv.w);
        vlo.x = fmaxf(vlo.x, nrm * q0.x);
        vlo.y = fmaxf(vlo.y, nrm * q0.y);
        vlo.z = fmaxf(vlo.z, nrm * q1.x);
        vlo.w = fmaxf(vlo.w, nrm * q1.y);
        vhi.x = fmaxf(vhi.x, nrm * q2.x);
        vhi.y = fmaxf(vhi.y, nrm * q2.y);
        vhi.z = fmaxf(vhi.z, nrm * q3.x);
        vhi.w = fmaxf(vhi.w, nrm * q3.y);
    }

    {   // self-loop term
        float  dd = d * d;
        uint4  hv = hp[(size_t)n * 30 + f];
        float2 q0 = __half22float2(*(const __half2*)&hv.x);
        float2 q1 = __half22float2(*(const __half2*)&hv.y);
        float2 q2 = __half22float2(*(const __half2*)&hv.z);
        float2 q3 = __half22float2(*(const __half2*)&hv.w);
        vlo.x = fmaxf(vlo.x, dd * q0.x);
        vlo.y = fmaxf(vlo.y, dd * q0.y);
        vlo.z = fmaxf(vlo.z, dd * q1.x);
        vlo.w = fmaxf(vlo.w, dd * q1.y);
        vhi.x = fmaxf(vhi.x, dd * q2.x);
        vhi.y = fmaxf(vhi.y, dd * q2.y);
        vhi.z = fmaxf(vhi.z, dd * q3.x);
        vhi.w = fmaxf(vhi.w, dd * q3.y);
    }

    if (lane < 30) {
        float4 b0 = ((const float4*)bias)[f * 2];
        float4 b1 = ((const float4*)bias)[f * 2 + 1];
        vlo.x = fmaxf(vlo.x + b0.x, 0.0f);
        vlo.y = fmaxf(vlo.y + b0.y, 0.0f);
        vlo.z = fmaxf(vlo.z + b0.z, 0.0f);
        vlo.w = fmaxf(vlo.w + b0.w, 0.0f);
        vhi.x = fmaxf(vhi.x + b1.x, 0.0f);
        vhi.y = fmaxf(vhi.y + b1.y, 0.0f);
        vhi.z = fmaxf(vhi.z + b1.z, 0.0f);
        vhi.w = fmaxf(vhi.w + b1.w, 0.0f);
        out4[(size_t)n * 60 + f * 2]     = vlo;
        out4[(size_t)n * 60 + f * 2 + 1] = vhi;
        // fp16 copy for the tensor-core GEMM
        __half2 h0 = __floats2half2_rn(vlo.x, vlo.y);
        __half2 h1 = __floats2half2_rn(vlo.z, vlo.w);
        __half2 h2 = __floats2half2_rn(vhi.x, vhi.y);
        __half2 h3 = __floats2half2_rn(vhi.z, vhi.w);
        uint4 u;
        u.x = *(unsigned*)&h0; u.y = *(unsigned*)&h1;
        u.z = *(unsigned*)&h2; u.w = *(unsigned*)&h3;
        outh[(size_t)n * 30 + f] = u;
    }
}

// ---------------- gemm2 via HMMA: g_aggH[M,240] @ g_W2h[240,240] -> g_bufH --
// BM=128, BN=80, BK=16, 256 thr. 8 warps = 4(M) x 2(N); warp tile 32x40.
// mma m16n8k16 f16f16->f32; per warp per k-step: 2(m) x 5(n) mma.
#define AS_LD 24   // As row pad (halfs)
#define BS_LD 88   // Bs row pad (halfs)

__device__ __forceinline__ void ldsm_x4(unsigned (&r)[4], unsigned addr) {
    asm volatile("ldmatrix.sync.aligned.m8n8.x4.shared.b16 {%0,%1,%2,%3}, [%4];"
                 : "=r"(r[0]), "=r"(r[1]), "=r"(r[2]), "=r"(r[3]) : "r"(addr));
}
__device__ __forceinline__ void ldsm_x2t(unsigned (&r)[2], unsigned addr) {
    asm volatile("ldmatrix.sync.aligned.m8n8.x2.trans.shared.b16 {%0,%1}, [%2];"
                 : "=r"(r[0]), "=r"(r[1]) : "r"(addr));
}
__device__ __forceinline__ void mma16816(float (&c)[4], const unsigned (&a)[4],
                                         const unsigned (&b)[2]) {
    asm volatile(
        "mma.sync.aligned.m16n8k16.row.col.f32.f16.f16.f32 "
        "{%0,%1,%2,%3}, {%4,%5,%6,%7}, {%8,%9}, {%0,%1,%2,%3};"
        : "+f"(c[0]), "+f"(c[1]), "+f"(c[2]), "+f"(c[3])
        : "r"(a[0]), "r"(a[1]), "r"(a[2]), "r"(a[3]), "r"(b[0]), "r"(b[1]));
}

__global__ void __launch_bounds__(256)
gemm2_mma_kernel(int M) {
    __shared__ __half As[128 * AS_LD];
    __shared__ __half Bs[16 * BS_LD];

    int tid  = threadIdx.x;
    int warp = tid >> 5;
    int lane = tid & 31;
    int wm = warp & 3;          // 0..3  (M: wm*32)
    int wn = warp >> 2;         // 0..1  (N: wn*40)
    int m0 = blockIdx.x * 128;
    int n0 = blockIdx.y * 80;

    const uint4* __restrict__ Ap = (const uint4*)g_aggH;   // 30 uint4/row
    const uint4* __restrict__ Bp = (const uint4*)g_W2h;    // 30 uint4/row

    float acc[2][5][4];
#pragma unroll
    for (int i = 0; i < 2; i++)
#pragma unroll
        for (int j = 0; j < 5; j++)
#pragma unroll
            for (int k = 0; k < 4; k++) acc[i][j][k] = 0.0f;

    // precompute ldmatrix smem byte addresses
    unsigned as_base = (unsigned)__cvta_generic_to_shared(As);
    unsigned bs_base = (unsigned)__cvta_generic_to_shared(Bs);
    int ai = lane & 7, as_sel = lane >> 3;
    int a_row_off = ai + ((as_sel & 1) ? 8 : 0);
    int a_k_off   = (as_sel & 2) ? 8 : 0;
    int lane16 = lane & 15;

    for (int kt = 0; kt < F_HID / 16; kt++) {
        // load A tile 128x16 (256 thr, one uint4 each)
        {
            int row = tid >> 1, seg = tid & 1;
            int grow = m0 + row;
            grow = grow < M ? grow : M - 1;
            uint4 v = Ap[(size_t)grow * 30 + kt * 2 + seg];
            *(uint4*)&As[row * AS_LD + seg * 8] = v;
        }
        // load B tile 16x80 (threads 0..159, one uint4 each)
        if (tid < 160) {
            int row = tid / 10, seg = tid % 10;
            uint4 v = Bp[(size_t)(kt * 16 + row) * 30 + blockIdx.y * 10 + seg];
            *(uint4*)&Bs[row * BS_LD + seg * 8] = v;
        }
        __syncthreads();

        unsigned afrag[2][4];
#pragma unroll
        for (int mt = 0; mt < 2; mt++) {
            int row = wm * 32 + mt * 16 + a_row_off;
            ldsm_x4(afrag[mt], as_base + (unsigned)((row * AS_LD + a_k_off) * 2));
        }
#pragma unroll
        for (int nt = 0; nt < 5; nt++) {
            unsigned bfrag[2];
            int ncol = wn * 40 + nt * 8;
            ldsm_x2t(bfrag, bs_base + (unsigned)((lane16 * BS_LD + ncol) * 2));
#pragma unroll
            for (int mt = 0; mt < 2; mt++) mma16816(acc[mt][nt], afrag[mt], bfrag);
        }
        __syncthreads();
    }

    // epilogue: fp16 into g_bufH [M, 240]
#pragma unroll
    for (int mt = 0; mt < 2; mt++) {
#pragma unroll
        for (int nt = 0; nt < 5; nt++) {
            int r0  = m0 + wm * 32 + mt * 16 + (lane >> 2);
            int col = n0 + wn * 40 + nt * 8 + (lane & 3) * 2;
            if (r0 < M) {
                __half2 h = __floats2half2_rn(acc[mt][nt][0], acc[mt][nt][1]);
                *(__half2*)&g_bufH[(size_t)r0 * F_HID + col] = h;
            }
            int r1 = r0 + 8;
            if (r1 < M) {
                __half2 h = __floats2half2_rn(acc[mt][nt][2], acc[mt][nt][3]);
                *(__half2*)&g_bufH[(size_t)r1 * F_HID + col] = h;
            }
        }
    }
}

// ---------------- head SGEMM (fp32 SIMT): g_bufB[M,240] @ We[240,80] + be ---
__global__ void __launch_bounds__(256, 2)
head_kernel(const float* __restrict__ B,
            const float* __restrict__ bias,
            float* __restrict__ Cout,
            int M, int Nn, int K) {
    const float* __restrict__ A = g_bufB;

    __shared__ float As2[16][129];
    __shared__ float Bs2[16][80];

    int tid = threadIdx.x;
    int ty = tid / 16, tx = tid % 16;
    int m0 = blockIdx.x * 128;
    int n0 = blockIdx.y * 80;

    float acc[8][5];
#pragma unroll
    for (int i = 0; i < 8; i++)
#pragma unroll
        for (int j = 0; j < 5; j++) acc[i][j] = 0.0f;

    for (int k0 = 0; k0 < K; k0 += 16) {
#pragma unroll
        for (int i = 0; i < 8; i++) {
            int l = tid + i * 256;
            int r = l >> 4, c = l & 15;
            int row = m0 + r;
            row = row < M ? row : M - 1;
            As2[c][r] = A[(size_t)row * K + k0 + c];
        }
#pragma unroll
        for (int i = 0; i < 5; i++) {
            int l = tid + i * 256;
            int r = l / 80, c = l - r * 80;
            Bs2[r][c] = B[(size_t)(k0 + r) * Nn + n0 + c];
        }
        __syncthreads();
#pragma unroll
        for (int kk = 0; kk < 16; kk++) {
            float a[8], b[5];
#pragma unroll
            for (int i = 0; i < 8; i++) a[i] = As2[kk][ty * 8 + i];
#pragma unroll
            for (int j = 0; j < 5; j++) b[j] = Bs2[kk][tx * 5 + j];
#pragma unroll
            for (int i = 0; i < 8; i++)
#pragma unroll
                for (int j = 0; j < 5; j++) acc[i][j] = fmaf(a[i], b[j], acc[i][j]);
        }
        __syncthreads();
    }

#pragma unroll
    for (int i = 0; i < 8; i++) {
        int row = m0 + ty * 8 + i;
        if (row < M) {
#pragma unroll
            for (int j = 0; j < 5; j++) {
                int col = n0 + tx * 5 + j;
                Cout[(size_t)row * Nn + col] = acc[i][j] + bias[col];
            }
        }
    }
}

// ---------------- launch ----------------------------------------------------
// Dataflow:
//   gemm1:     x @ W1                  -> bufH (fp16)
//   agg :      relu(max-agg(bufH)+b1)  -> bufB (fp32) + aggH (fp16)
//   gemm2_mma: aggH @ W2h (HMMA)       -> bufH (fp16)
//   agg :      relu(max-agg(bufH)+b2)  -> bufB (fp32) + aggH
//   head :     bufB @ We + be          -> out  (fp32)
extern "C" void kernel_launch(void* const* d_in, const int* in_sizes, int n_in,
                              void* d_out, int out_size) {
    const float* x  = (const float*)d_in[0];
    const int*   ei = (const int*)d_in[1];     // int32 (JAX x64 disabled)
    const float* ew = (const float*)d_in[2];
    const float* W1 = (const float*)d_in[3];
    const float* b1 = (const float*)d_in[4];
    const float* W2 = (const float*)d_in[5];
    const float* b2 = (const float*)d_in[6];
    const float* We = (const float*)d_in[7];
    const float* be = (const float*)d_in[8];
    float* out = (float*)d_out;

    const int TB = 256;
    int gN = (N_NODES + TB - 1) / TB;
    int gE = (N_EDGES + TB - 1) / TB;

    // graph structure (shared by both layers)
    zero_kernel<<<gN, TB>>>();
    deg_kernel<<<gE, TB>>>(ei, ew);
    scan1_kernel<<<SCAN_G, SCAN_B>>>();
    scan2_kernel<<<1, SCAN_B>>>();
    scan3_kernel<<<SCAN_G, SCAN_B>>>();
    fill_kernel<<<gE, TB>>>(ei, ew);
    cvtW2_kernel<<<(F_HID * F_HID / 4 + TB - 1) / TB, TB>>>(W2);

    // layer 1
    gemm1_kernel<<<(N_NODES * 60 + TB - 1) / TB, TB>>>(x, W1);
    agg_kernel<<<(N_NODES + 7) / 8, 256>>>(b1);

    // layer 2 (tensor cores)
    {
        dim3 grid((N_NODES + 127) / 128, F_HID / 80);
        gemm2_mma_kernel<<<grid, 256>>>(N_NODES);
    }
    agg_kernel<<<(N_NODES + 7) / 8, 256>>>(b2);

    // head
    {
        dim3 grid((N_NODES + 127) / 128, F_OUT / 80);
        head_kernel<<<grid, 256>>>(We, be, out, N_NODES, F_OUT, F_HID);
    }
}

// round 11
// speedup vs baseline: 2.3434x; 1.2183x over previous
#include <cuda_runtime.h>
#include <cuda_fp16.h>
#include <float.h>

#define N_NODES 50000
#define N_EDGES 1600000
#define F_HID   240
#define F_OUT   80
#define SCAN_B  256
#define SCAN_G  ((N_NODES + SCAN_B - 1) / SCAN_B)   // 196

// ---------------- scratch (device globals; no allocation allowed) ----------
__device__ float  g_deg[N_NODES];
__device__ float  g_dis[N_NODES];
__device__ int    g_cnt[N_NODES];
__device__ int    g_off[N_NODES];
__device__ int    g_cur[N_NODES];
__device__ int    g_blksum[SCAN_G];
__device__ int    g_blkoff[SCAN_G];
__device__ int2   g_edge[N_EDGES];                    // (src, nrm bits)
__device__ __half g_bufH[(size_t)N_NODES * F_HID];    // pre-agg features, fp16
__device__ __half g_aggH[(size_t)N_NODES * F_HID];    // agg outputs, fp16
__device__ __half g_W2h[F_HID * F_HID];               // W2 in fp16
__device__ __half g_Weh[F_HID * F_OUT];               // We in fp16

// ---------------- graph preprocessing --------------------------------------
__global__ void zero_kernel() {
    int i = blockIdx.x * blockDim.x + threadIdx.x;
    if (i < N_NODES) { g_deg[i] = 0.0f; g_cnt[i] = 0; }
}

__global__ void deg_kernel(const int* __restrict__ ei,
                           const float* __restrict__ ew) {
    int e = blockIdx.x * blockDim.x + threadIdx.x;
    if (e < N_EDGES) {
        int c = ei[N_EDGES + e];
        if ((unsigned)c < N_NODES) {
            atomicAdd(&g_deg[c], ew[e]);
            atomicAdd(&g_cnt[c], 1);
        }
    }
}

// ---- parallel exclusive scan of g_cnt -> g_off / g_cur (3 phases) ---------
__global__ void scan1_kernel() {
    __shared__ int s[SCAN_B];
    int t = threadIdx.x;
    int i = blockIdx.x * SCAN_B + t;
    int v = 0;
    if (i < N_NODES) {
        v = g_cnt[i];
        g_dis[i] = rsqrtf(g_deg[i] + 1.0f);  // +1 = self loop
    }
    s[t] = v;
    __syncthreads();
    for (int d = SCAN_B / 2; d > 0; d >>= 1) {
        if (t < d) s[t] += s[t + d];
        __syncthreads();
    }
    if (t == 0) g_blksum[blockIdx.x] = s[0];
}

__global__ void scan2_kernel() {
    __shared__ int s[SCAN_B];
    int t = threadIdx.x;
    int v = (t < SCAN_G) ? g_blksum[t] : 0;
    s[t] = v;
    __syncthreads();
    for (int d = 1; d < SCAN_B; d <<= 1) {
        int u = (t >= d) ? s[t - d] : 0;
        __syncthreads();
        s[t] += u;
        __syncthreads();
    }
    if (t < SCAN_G) g_blkoff[t] = s[t] - v;
}

__global__ void scan3_kernel() {
    __shared__ int s[SCAN_B];
    int t = threadIdx.x;
    int i = blockIdx.x * SCAN_B + t;
    int v = (i < N_NODES) ? g_cnt[i] : 0;
    s[t] = v;
    __syncthreads();
    for (int d = 1; d < SCAN_B; d <<= 1) {
        int u = (t >= d) ? s[t - d] : 0;
        __syncthreads();
        s[t] += u;
        __syncthreads();
    }
    if (i < N_NODES) {
        int excl = s[t] - v + g_blkoff[blockIdx.x];
        g_off[i] = excl;
        g_cur[i] = excl;
    }
}

__global__ void fill_kernel(const int* __restrict__ ei,
                            const float* __restrict__ ew) {
    int e = blockIdx.x * blockDim.x + threadIdx.x;
    if (e < N_EDGES) {
        int r = ei[e];
        int c = ei[N_EDGES + e];
        if ((unsigned)r < N_NODES && (unsigned)c < N_NODES) {
            float nrm = g_dis[r] * ew[e] * g_dis[c];
            int p = atomicAdd(&g_cur[c], 1);
            g_edge[p] = make_int2(r, __float_as_int(nrm));
        }
    }
}

// ---------------- weight fp16 conversion (once per launch) ------------------
__global__ void cvtW_kernel(const float* __restrict__ W2,
                            const float* __restrict__ We) {
    int i = blockIdx.x * blockDim.x + threadIdx.x;
    const int N2 = F_HID * F_HID / 4;             // 14400
    const int NE = F_HID * F_OUT / 4;             // 4800
    if (i < N2) {
        float4 v = ((const float4*)W2)[i];
        __half2 p0 = __floats2half2_rn(v.x, v.y);
        __half2 p1 = __floats2half2_rn(v.z, v.w);
        uint2 u; u.x = *(unsigned*)&p0; u.y = *(unsigned*)&p1;
        ((uint2*)g_W2h)[i] = u;
    } else if (i < N2 + NE) {
        int j = i - N2;
        float4 v = ((const float4*)We)[j];
        __half2 p0 = __floats2half2_rn(v.x, v.y);
        __half2 p1 = __floats2half2_rn(v.z, v.w);
        uint2 u; u.x = *(unsigned*)&p0; u.y = *(unsigned*)&p1;
        ((uint2*)g_Weh)[j] = u;
    }
}

// ---------------- GEMM1: [N,5] @ [5,240] -> g_bufH (fp16) ------------------
__global__ void gemm1_kernel(const float* __restrict__ x,
                             const float* __restrict__ W1) {
    int idx = blockIdx.x * blockDim.x + threadIdx.x;   // [0, N*60)
    if (idx >= N_NODES * 60) return;
    int n = idx / 60, q = idx - n * 60;
    const float* xr = x + n * 5;
    float a0 = 0, a1 = 0, a2 = 0, a3 = 0;
#pragma unroll
    for (int k = 0; k < 5; k++) {
        float xv = xr[k];
        const float* w = W1 + k * F_HID + q * 4;
        a0 = fmaf(xv, w[0], a0);
        a1 = fmaf(xv, w[1], a1);
        a2 = fmaf(xv, w[2], a2);
        a3 = fmaf(xv, w[3], a3);
    }
    __half2 p0 = __floats2half2_rn(a0, a1);
    __half2 p1 = __floats2half2_rn(a2, a3);
    uint2 u;
    u.x = *(unsigned*)&p0;
    u.y = *(unsigned*)&p1;
    ((uint2*)g_bufH)[idx] = u;
}

// ---------------- scatter-max aggregation: WARP PER NODE --------------------
// Reads g_bufH (fp16), fp32 compute, writes fp16 relu(max+bias) to g_aggH.
__global__ void __launch_bounds__(256, 8)
agg_kernel(const float* __restrict__ bias) {
    const uint4* __restrict__ hp   = (const uint4*)g_bufH;   // 30 uint4 / row
    uint4* __restrict__       outh = (uint4*)g_aggH;         // 30 uint4 / row

    int warp = threadIdx.x >> 5;
    int lane = threadIdx.x & 31;
    int n = blockIdx.x * 8 + warp;
    if (n >= N_NODES) return;
    int f = lane < 30 ? lane : 29;

    int   start = g_off[n];
    int   cnt   = g_cnt[n];
    float d     = g_dis[n];

    float4 vlo = make_float4(-FLT_MAX, -FLT_MAX, -FLT_MAX, -FLT_MAX);
    float4 vhi = vlo;

    const int2* __restrict__ ep = g_edge + start;
#pragma unroll 4
    for (int e = 0; e < cnt; e++) {
        int2   ed  = __ldg(&ep[e]);
        float  nrm = __int_as_float(ed.y);
        uint4  hv  = hp[(size_t)ed.x * 30 + f];
        float2 q0 = __half22float2(*(const __half2*)&hv.x);
        float2 q1 = __half22float2(*(const __half2*)&hv.y);
        float2 q2 = __half22float2(*(const __half2*)&hv.z);
        float2 q3 = __half22float2(*(const __half2*)&hv.w);
        vlo.x = fmaxf(vlo.x, nrm * q0.x);
        vlo.y = fmaxf(vlo.y, nrm * q0.y);
        vlo.z = fmaxf(vlo.z, nrm * q1.x);
        vlo.w = fmaxf(vlo.w, nrm * q1.y);
        vhi.x = fmaxf(vhi.x, nrm * q2.x);
        vhi.y = fmaxf(vhi.y, nrm * q2.y);
        vhi.z = fmaxf(vhi.z, nrm * q3.x);
        vhi.w = fmaxf(vhi.w, nrm * q3.y);
    }

    {   // self-loop term
        float  dd = d * d;
        uint4  hv = hp[(size_t)n * 30 + f];
        float2 q0 = __half22float2(*(const __half2*)&hv.x);
        float2 q1 = __half22float2(*(const __half2*)&hv.y);
        float2 q2 = __half22float2(*(const __half2*)&hv.z);
        float2 q3 = __half22float2(*(const __half2*)&hv.w);
        vlo.x = fmaxf(vlo.x, dd * q0.x);
        vlo.y = fmaxf(vlo.y, dd * q0.y);
        vlo.z = fmaxf(vlo.z, dd * q1.x);
        vlo.w = fmaxf(vlo.w, dd * q1.y);
        vhi.x = fmaxf(vhi.x, dd * q2.x);
        vhi.y = fmaxf(vhi.y, dd * q2.y);
        vhi.z = fmaxf(vhi.z, dd * q3.x);
        vhi.w = fmaxf(vhi.w, dd * q3.y);
    }

    if (lane < 30) {
        float4 b0 = ((const float4*)bias)[f * 2];
        float4 b1 = ((const float4*)bias)[f * 2 + 1];
        vlo.x = fmaxf(vlo.x + b0.x, 0.0f);
        vlo.y = fmaxf(vlo.y + b0.y, 0.0f);
        vlo.z = fmaxf(vlo.z + b0.z, 0.0f);
        vlo.w = fmaxf(vlo.w + b0.w, 0.0f);
        vhi.x = fmaxf(vhi.x + b1.x, 0.0f);
        vhi.y = fmaxf(vhi.y + b1.y, 0.0f);
        vhi.z = fmaxf(vhi.z + b1.z, 0.0f);
        vhi.w = fmaxf(vhi.w + b1.w, 0.0f);
        __half2 h0 = __floats2half2_rn(vlo.x, vlo.y);
        __half2 h1 = __floats2half2_rn(vlo.z, vlo.w);
        __half2 h2 = __floats2half2_rn(vhi.x, vhi.y);
        __half2 h3 = __floats2half2_rn(vhi.z, vhi.w);
        uint4 u;
        u.x = *(unsigned*)&h0; u.y = *(unsigned*)&h1;
        u.z = *(unsigned*)&h2; u.w = *(unsigned*)&h3;
        outh[(size_t)n * 30 + f] = u;
    }
}

// ---------------- HMMA GEMM: g_aggH[M,240] @ Wh[240,Nn] ---------------------
// BM=128, BN=80, BK=16, 256 thr. 8 warps = 4(M) x 2(N); warp tile 32x40.
// DST=0: B=g_W2h (Nn=240, slice by blockIdx.y), out fp16 -> g_bufH.
// DST=1: B=g_Weh (Nn=80), out fp32 + bias -> Cout.
#define AS_LD 24   // As row pad (halfs)
#define BS_LD 88   // Bs row pad (halfs)

__device__ __forceinline__ void ldsm_x4(unsigned (&r)[4], unsigned addr) {
    asm volatile("ldmatrix.sync.aligned.m8n8.x4.shared.b16 {%0,%1,%2,%3}, [%4];"
                 : "=r"(r[0]), "=r"(r[1]), "=r"(r[2]), "=r"(r[3]) : "r"(addr));
}
__device__ __forceinline__ void ldsm_x2t(unsigned (&r)[2], unsigned addr) {
    asm volatile("ldmatrix.sync.aligned.m8n8.x2.trans.shared.b16 {%0,%1}, [%2];"
                 : "=r"(r[0]), "=r"(r[1]) : "r"(addr));
}
__device__ __forceinline__ void mma16816(float (&c)[4], const unsigned (&a)[4],
                                         const unsigned (&b)[2]) {
    asm volatile(
        "mma.sync.aligned.m16n8k16.row.col.f32.f16.f16.f32 "
        "{%0,%1,%2,%3}, {%4,%5,%6,%7}, {%8,%9}, {%0,%1,%2,%3};"
        : "+f"(c[0]), "+f"(c[1]), "+f"(c[2]), "+f"(c[3])
        : "r"(a[0]), "r"(a[1]), "r"(a[2]), "r"(a[3]), "r"(b[0]), "r"(b[1]));
}

template <int DST>
__global__ void __launch_bounds__(256)
gemm_mma_kernel(const float* __restrict__ bias,
                float* __restrict__ Cout, int M) {
    __shared__ __half As[128 * AS_LD];
    __shared__ __half Bs[16 * BS_LD];

    const int Nn      = DST == 0 ? F_HID : F_OUT;   // 240 or 80
    const int BSTRIDE = Nn / 8;                     // uint4 per B row

    int tid  = threadIdx.x;
    int warp = tid >> 5;
    int lane = tid & 31;
    int wm = warp & 3;
    int wn = warp >> 2;
    int m0 = blockIdx.x * 128;
    int n0 = blockIdx.y * 80;

    const uint4* __restrict__ Ap = (const uint4*)g_aggH;
    const uint4* __restrict__ Bp = (const uint4*)(DST == 0 ? g_W2h : g_Weh);

    float acc[2][5][4];
#pragma unroll
    for (int i = 0; i < 2; i++)
#pragma unroll
        for (int j = 0; j < 5; j++)
#pragma unroll
            for (int k = 0; k < 4; k++) acc[i][j][k] = 0.0f;

    unsigned as_base = (unsigned)__cvta_generic_to_shared(As);
    unsigned bs_base = (unsigned)__cvta_generic_to_shared(Bs);
    int ai = lane & 7, as_sel = lane >> 3;
    int a_row_off = ai + ((as_sel & 1) ? 8 : 0);
    int a_k_off   = (as_sel & 2) ? 8 : 0;
    int lane16 = lane & 15;

    for (int kt = 0; kt < F_HID / 16; kt++) {
        {   // load A tile 128x16
            int row = tid >> 1, seg = tid & 1;
            int grow = m0 + row;
            grow = grow < M ? grow : M - 1;
            uint4 v = Ap[(size_t)grow * 30 + kt * 2 + seg];
            *(uint4*)&As[row * AS_LD + seg * 8] = v;
        }
        if (tid < 160) {   // load B tile 16x80
            int row = tid / 10, seg = tid % 10;
            uint4 v = Bp[(size_t)(kt * 16 + row) * BSTRIDE + blockIdx.y * 10 + seg];
            *(uint4*)&Bs[row * BS_LD + seg * 8] = v;
        }
        __syncthreads();

        unsigned afrag[2][4];
#pragma unroll
        for (int mt = 0; mt < 2; mt++) {
            int row = wm * 32 + mt * 16 + a_row_off;
            ldsm_x4(afrag[mt], as_base + (unsigned)((row * AS_LD + a_k_off) * 2));
        }
#pragma unroll
        for (int nt = 0; nt < 5; nt++) {
            unsigned bfrag[2];
            int ncol = wn * 40 + nt * 8;
            ldsm_x2t(bfrag, bs_base + (unsigned)((lane16 * BS_LD + ncol) * 2));
#pragma unroll
            for (int mt = 0; mt < 2; mt++) mma16816(acc[mt][nt], afrag[mt], bfrag);
        }
        __syncthreads();
    }

#pragma unroll
    for (int mt = 0; mt < 2; mt++) {
#pragma unroll
        for (int nt = 0; nt < 5; nt++) {
            int r0  = m0 + wm * 32 + mt * 16 + (lane >> 2);
            int col = n0 + wn * 40 + nt * 8 + (lane & 3) * 2;
            if (DST == 0) {
                if (r0 < M) {
                    __half2 h = __floats2half2_rn(acc[mt][nt][0], acc[mt][nt][1]);
                    *(__half2*)&g_bufH[(size_t)r0 * F_HID + col] = h;
                }
                int r1 = r0 + 8;
                if (r1 < M) {
                    __half2 h = __floats2half2_rn(acc[mt][nt][2], acc[mt][nt][3]);
                    *(__half2*)&g_bufH[(size_t)r1 * F_HID + col] = h;
                }
            } else {
                float bx = bias[col], by = bias[col + 1];
                if (r0 < M) {
                    float2 o = make_float2(acc[mt][nt][0] + bx, acc[mt][nt][1] + by);
                    *(float2*)&Cout[(size_t)r0 * F_OUT + col] = o;
                }
                int r1 = r0 + 8;
                if (r1 < M) {
                    float2 o = make_float2(acc[mt][nt][2] + bx, acc[mt][nt][3] + by);
                    *(float2*)&Cout[(size_t)r1 * F_OUT + col] = o;
                }
            }
        }
    }
}

// ---------------- launch ----------------------------------------------------
// Dataflow:
//   gemm1:        x @ W1                  -> bufH (fp16)
//   agg :         relu(max-agg(bufH)+b1)  -> aggH (fp16)
//   gemm_mma<0>:  aggH @ W2h (HMMA)       -> bufH (fp16)
//   agg :         relu(max-agg(bufH)+b2)  -> aggH (fp16)
//   gemm_mma<1>:  aggH @ Weh + be (HMMA)  -> out  (fp32)
extern "C" void kernel_launch(void* const* d_in, const int* in_sizes, int n_in,
                              void* d_out, int out_size) {
    const float* x  = (const float*)d_in[0];
    const int*   ei = (const int*)d_in[1];     // int32 (JAX x64 disabled)
    const float* ew = (const float*)d_in[2];
    const float* W1 = (const float*)d_in[3];
    const float* b1 = (const float*)d_in[4];
    const float* W2 = (const float*)d_in[5];
    const float* b2 = (const float*)d_in[6];
    const float* We = (const float*)d_in[7];
    const float* be = (const float*)d_in[8];
    float* out = (float*)d_out;

    const int TB = 256;
    int gN = (N_NODES + TB - 1) / TB;
    int gE = (N_EDGES + TB - 1) / TB;

    // graph structure (shared by both layers)
    zero_kernel<<<gN, TB>>>();
    deg_kernel<<<gE, TB>>>(ei, ew);
    scan1_kernel<<<SCAN_G, SCAN_B>>>();
    scan2_kernel<<<1, SCAN_B>>>();
    scan3_kernel<<<SCAN_G, SCAN_B>>>();
    fill_kernel<<<gE, TB>>>(ei, ew);
    cvtW_kernel<<<(F_HID * F_HID / 4 + F_HID * F_OUT / 4 + TB - 1) / TB, TB>>>(W2, We);

    // layer 1
    gemm1_kernel<<<(N_NODES * 60 + TB - 1) / TB, TB>>>(x, W1);
    agg_kernel<<<(N_NODES + 7) / 8, 256>>>(b1);

    // layer 2 (tensor cores)
    {
        dim3 grid((N_NODES + 127) / 128, F_HID / 80);
        gemm_mma_kernel<0><<<grid, 256>>>(nullptr, nullptr, N_NODES);
    }
    agg_kernel<<<(N_NODES + 7) / 8, 256>>>(b2);

    // head (tensor cores, fp32 out)
    {
        dim3 grid((N_NODES + 127) / 128, 1);
        gemm_mma_kernel<1><<<grid, 256>>>(be, out, N_NODES);
    }
}

// round 12
// speedup vs baseline: 2.4642x; 1.0515x over previous
#include <cuda_runtime.h>
#include <cuda_fp16.h>
#include <float.h>

#define N_NODES 50000
#define N_EDGES 1600000
#define F_HID   240
#define F_OUT   80
#define SCAN_B  256
#define SCAN_G  ((N_NODES + SCAN_B - 1) / SCAN_B)   // 196

#define CNT_SHIFT 42
#define DEG_MASK  ((1ULL << CNT_SHIFT) - 1)
#define DEG_SCALE (1.0f / 4294967296.0f)

// ---------------- scratch (device globals; no allocation allowed) ----------
__device__ unsigned long long g_degcnt[N_NODES];   // fixed-point deg | cnt<<42
__device__ unsigned long long g_scanst[SCAN_G];    // lookback: state<<62 | val
__device__ float  g_dis[N_NODES];
__device__ int    g_cnt[N_NODES];
__device__ int    g_off[N_NODES];
__device__ int    g_cur[N_NODES];
__device__ int2   g_edge[N_EDGES];                    // (src, nrm bits)
__device__ __half g_bufH[(size_t)N_NODES * F_HID];    // pre-agg features, fp16
__device__ __half g_aggH[(size_t)N_NODES * F_HID];    // agg outputs, fp16
__device__ __half g_W2h[F_HID * F_HID];               // W2 in fp16
__device__ __half g_Weh[F_HID * F_OUT];               // We in fp16

// ---------------- graph preprocessing --------------------------------------
__global__ void zero_kernel() {
    int i = blockIdx.x * blockDim.x + threadIdx.x;
    if (i < N_NODES) g_degcnt[i] = 0ULL;
    if (i < SCAN_G)  g_scanst[i] = 0ULL;
}

// one packed 64-bit atomic per edge: deg (32.10 fixed point) + cnt (bits 42+)
__global__ void deg_kernel(const int* __restrict__ ei,
                           const float* __restrict__ ew) {
    int e = blockIdx.x * blockDim.x + threadIdx.x;
    if (e < N_EDGES) {
        int c = ei[N_EDGES + e];
        if ((unsigned)c < N_NODES) {
            unsigned long long add =
                __float2ull_rn(ew[e] * 4294967296.0f) | (1ULL << CNT_SHIFT);
            atomicAdd(&g_degcnt[c], add);
        }
    }
}

// ---- single-pass decoupled-lookback exclusive scan of cnt ------------------
// Also extracts cnt, computes dis. 196 blocks — all resident in wave 1.
__global__ void scan_kernel() {
    __shared__ int s[SCAN_B];
    __shared__ int s_excl;
    int b = blockIdx.x, t = threadIdx.x;
    int i = b * SCAN_B + t;

    int cnt = 0;
    if (i < N_NODES) {
        unsigned long long p = g_degcnt[i];
        cnt = (int)(p >> CNT_SHIFT);
        g_dis[i] = rsqrtf((float)(p & DEG_MASK) * DEG_SCALE + 1.0f);
    }
    s[t] = cnt;
    __syncthreads();
    for (int d = 1; d < SCAN_B; d <<= 1) {
        int u = (t >= d) ? s[t - d] : 0;
        __syncthreads();
        s[t] += u;
        __syncthreads();
    }
    int incl = s[t];

    if (t == 0) {
        int total = s[SCAN_B - 1];
        if (b == 0) {
            s_excl = 0;
            atomicExch(&g_scanst[0], (2ULL << 62) | (unsigned)total);
        } else {
            // publish aggregate first, then look back
            atomicExch(&g_scanst[b], (1ULL << 62) | (unsigned)total);
            long long run = 0;
            int p = b - 1;
            while (true) {
                unsigned long long w = atomicAdd(&g_scanst[p], 0ULL);
                unsigned st = (unsigned)(w >> 62);
                if (st == 2u) { run += (unsigned)(w & 0xFFFFFFFFu); break; }
                if (st == 1u) { run += (unsigned)(w & 0xFFFFFFFFu); p--; }
            }
            s_excl = (int)run;
            atomicExch(&g_scanst[b],
                       (2ULL << 62) | (unsigned)(run + total));
        }
    }
    __syncthreads();

    if (i < N_NODES) {
        int excl = s_excl + incl - cnt;
        g_off[i] = excl;
        g_cur[i] = excl;
        g_cnt[i] = cnt;
    }
}

__global__ void fill_kernel(const int* __restrict__ ei,
                            const float* __restrict__ ew) {
    int e = blockIdx.x * blockDim.x + threadIdx.x;
    if (e < N_EDGES) {
        int r = ei[e];
        int c = ei[N_EDGES + e];
        if ((unsigned)r < N_NODES && (unsigned)c < N_NODES) {
            float nrm = g_dis[r] * ew[e] * g_dis[c];
            int p = atomicAdd(&g_cur[c], 1);
            g_edge[p] = make_int2(r, __float_as_int(nrm));
        }
    }
}

// ---------------- weight fp16 conversion (once per launch) ------------------
__global__ void cvtW_kernel(const float* __restrict__ W2,
                            const float* __restrict__ We) {
    int i = blockIdx.x * blockDim.x + threadIdx.x;
    const int N2 = F_HID * F_HID / 4;             // 14400
    const int NE = F_HID * F_OUT / 4;             // 4800
    if (i < N2) {
        float4 v = ((const float4*)W2)[i];
        __half2 p0 = __floats2half2_rn(v.x, v.y);
        __half2 p1 = __floats2half2_rn(v.z, v.w);
        uint2 u; u.x = *(unsigned*)&p0; u.y = *(unsigned*)&p1;
        ((uint2*)g_W2h)[i] = u;
    } else if (i < N2 + NE) {
        int j = i - N2;
        float4 v = ((const float4*)We)[j];
        __half2 p0 = __floats2half2_rn(v.x, v.y);
        __half2 p1 = __floats2half2_rn(v.z, v.w);
        uint2 u; u.x = *(unsigned*)&p0; u.y = *(unsigned*)&p1;
        ((uint2*)g_Weh)[j] = u;
    }
}

// ---------------- GEMM1: [N,5] @ [5,240] -> g_bufH (fp16) ------------------
__global__ void gemm1_kernel(const float* __restrict__ x,
                             const float* __restrict__ W1) {
    int idx = blockIdx.x * blockDim.x + threadIdx.x;   // [0, N*60)
    if (idx >= N_NODES * 60) return;
    int n = idx / 60, q = idx - n * 60;
    const float* xr = x + n * 5;
    float a0 = 0, a1 = 0, a2 = 0, a3 = 0;
#pragma unroll
    for (int k = 0; k < 5; k++) {
        float xv = xr[k];
        const float* w = W1 + k * F_HID + q * 4;
        a0 = fmaf(xv, w[0], a0);
        a1 = fmaf(xv, w[1], a1);
        a2 = fmaf(xv, w[2], a2);
        a3 = fmaf(xv, w[3], a3);
    }
    __half2 p0 = __floats2half2_rn(a0, a1);
    __half2 p1 = __floats2half2_rn(a2, a3);
    uint2 u;
    u.x = *(unsigned*)&p0;
    u.y = *(unsigned*)&p1;
    ((uint2*)g_bufH)[idx] = u;
}

// ---------------- scatter-max aggregation: WARP PER NODE --------------------
__global__ void __launch_bounds__(256, 8)
agg_kernel(const float* __restrict__ bias) {
    const uint4* __restrict__ hp   = (const uint4*)g_bufH;   // 30 uint4 / row
    uint4* __restrict__       outh = (uint4*)g_aggH;         // 30 uint4 / row

    int warp = threadIdx.x >> 5;
    int lane = threadIdx.x & 31;
    int n = blockIdx.x * 8 + warp;
    if (n >= N_NODES) return;
    int f = lane < 30 ? lane : 29;

    int   start = g_off[n];
    int   cnt   = g_cnt[n];
    float d     = g_dis[n];

    float4 vlo = make_float4(-FLT_MAX, -FLT_MAX, -FLT_MAX, -FLT_MAX);
    float4 vhi = vlo;

    const int2* __restrict__ ep = g_edge + start;
#pragma unroll 4
    for (int e = 0; e < cnt; e++) {
        int2   ed  = __ldg(&ep[e]);
        float  nrm = __int_as_float(ed.y);
        uint4  hv  = hp[(size_t)ed.x * 30 + f];
        float2 q0 = __half22float2(*(const __half2*)&hv.x);
        float2 q1 = __half22float2(*(const __half2*)&hv.y);
        float2 q2 = __half22float2(*(const __half2*)&hv.z);
        float2 q3 = __half22float2(*(const __half2*)&hv.w);
        vlo.x = fmaxf(vlo.x, nrm * q0.x);
        vlo.y = fmaxf(vlo.y, nrm * q0.y);
        vlo.z = fmaxf(vlo.z, nrm * q1.x);
        vlo.w = fmaxf(vlo.w, nrm * q1.y);
        vhi.x = fmaxf(vhi.x, nrm * q2.x);
        vhi.y = fmaxf(vhi.y, nrm * q2.y);
        vhi.z = fmaxf(vhi.z, nrm * q3.x);
        vhi.w = fmaxf(vhi.w, nrm * q3.y);
    }

    {   // self-loop term
        float  dd = d * d;
        uint4  hv = hp[(size_t)n * 30 + f];
        float2 q0 = __half22float2(*(const __half2*)&hv.x);
        float2 q1 = __half22float2(*(const __half2*)&hv.y);
        float2 q2 = __half22float2(*(const __half2*)&hv.z);
        float2 q3 = __half22float2(*(const __half2*)&hv.w);
        vlo.x = fmaxf(vlo.x, dd * q0.x);
        vlo.y = fmaxf(vlo.y, dd * q0.y);
        vlo.z = fmaxf(vlo.z, dd * q1.x);
        vlo.w = fmaxf(vlo.w, dd * q1.y);
        vhi.x = fmaxf(vhi.x, dd * q2.x);
        vhi.y = fmaxf(vhi.y, dd * q2.y);
        vhi.z = fmaxf(vhi.z, dd * q3.x);
        vhi.w = fmaxf(vhi.w, dd * q3.y);
    }

    if (lane < 30) {
        float4 b0 = ((const float4*)bias)[f * 2];
        float4 b1 = ((const float4*)bias)[f * 2 + 1];
        vlo.x = fmaxf(vlo.x + b0.x, 0.0f);
        vlo.y = fmaxf(vlo.y + b0.y, 0.0f);
        vlo.z = fmaxf(vlo.z + b0.z, 0.0f);
        vlo.w = fmaxf(vlo.w + b0.w, 0.0f);
        vhi.x = fmaxf(vhi.x + b1.x, 0.0f);
        vhi.y = fmaxf(vhi.y + b1.y, 0.0f);
        vhi.z = fmaxf(vhi.z + b1.z, 0.0f);
        vhi.w = fmaxf(vhi.w + b1.w, 0.0f);
        __half2 h0 = __floats2half2_rn(vlo.x, vlo.y);
        __half2 h1 = __floats2half2_rn(vlo.z, vlo.w);
        __half2 h2 = __floats2half2_rn(vhi.x, vhi.y);
        __half2 h3 = __floats2half2_rn(vhi.z, vhi.w);
        uint4 u;
        u.x = *(unsigned*)&h0; u.y = *(unsigned*)&h1;
        u.z = *(unsigned*)&h2; u.w = *(unsigned*)&h3;
        outh[(size_t)n * 30 + f] = u;
    }
}

// ---------------- HMMA GEMM: g_aggH[M,240] @ Wh[240,Nn], BK=48 --------------
// BM=128, BN=80, BK=48 (240 = 5*48), 256 thr. 8 warps = 4(M) x 2(N).
// DST=0: B=g_W2h (Nn=240, slice by blockIdx.y), out fp16 -> g_bufH.
// DST=1: B=g_Weh (Nn=80), out fp32 + bias -> Cout.
#define AS_LD 56   // 48 + 8 pad (halfs)
#define BS_LD 88   // 80 + 8 pad (halfs)

__device__ __forceinline__ void ldsm_x4(unsigned (&r)[4], unsigned addr) {
    asm volatile("ldmatrix.sync.aligned.m8n8.x4.shared.b16 {%0,%1,%2,%3}, [%4];"
                 : "=r"(r[0]), "=r"(r[1]), "=r"(r[2]), "=r"(r[3]) : "r"(addr));
}
__device__ __forceinline__ void ldsm_x2t(unsigned (&r)[2], unsigned addr) {
    asm volatile("ldmatrix.sync.aligned.m8n8.x2.trans.shared.b16 {%0,%1}, [%2];"
                 : "=r"(r[0]), "=r"(r[1]) : "r"(addr));
}
__device__ __forceinline__ void mma16816(float (&c)[4], const unsigned (&a)[4],
                                         const unsigned (&b)[2]) {
    asm volatile(
        "mma.sync.aligned.m16n8k16.row.col.f32.f16.f16.f32 "
        "{%0,%1,%2,%3}, {%4,%5,%6,%7}, {%8,%9}, {%0,%1,%2,%3};"
        : "+f"(c[0]), "+f"(c[1]), "+f"(c[2]), "+f"(c[3])
        : "r"(a[0]), "r"(a[1]), "r"(a[2]), "r"(a[3]), "r"(b[0]), "r"(b[1]));
}

template <int DST>
__global__ void __launch_bounds__(256)
gemm_mma_kernel(const float* __restrict__ bias,
                float* __restrict__ Cout, int M) {
    __shared__ __half As[128 * AS_LD];   // 14336 B
    __shared__ __half Bs[48 * BS_LD];    //  8448 B

    const int Nn      = DST == 0 ? F_HID : F_OUT;   // 240 or 80
    const int BSTRIDE = Nn / 8;                     // uint4 per B row

    int tid  = threadIdx.x;
    int warp = tid >> 5;
    int lane = tid & 31;
    int wm = warp & 3;
    int wn = warp >> 2;
    int m0 = blockIdx.x * 128;
    int n0 = blockIdx.y * 80;

    const uint4* __restrict__ Ap = (const uint4*)g_aggH;
    const uint4* __restrict__ Bp = (const uint4*)(DST == 0 ? g_W2h : g_Weh);

    float acc[2][5][4];
#pragma unroll
    for (int i = 0; i < 2; i++)
#pragma unroll
        for (int j = 0; j < 5; j++)
#pragma unroll
            for (int k = 0; k < 4; k++) acc[i][j][k] = 0.0f;

    unsigned as_base = (unsigned)__cvta_generic_to_shared(As);
    unsigned bs_base = (unsigned)__cvta_generic_to_shared(Bs);
    int ai = lane & 7, as_sel = lane >> 3;
    int a_row_off = ai + ((as_sel & 1) ? 8 : 0);
    int a_k_sub   = (as_sel & 2) ? 8 : 0;
    int lane16 = lane & 15;

    for (int kt = 0; kt < 5; kt++) {
        // load A tile 128x48 halfs: 768 uint4, 3 per thread
#pragma unroll
        for (int j = 0; j < 3; j++) {
            int i = tid + 256 * j;
            int row = i / 6, seg = i - row * 6;
            int grow = m0 + row;
            grow = grow < M ? grow : M - 1;
            uint4 v = Ap[(size_t)grow * 30 + kt * 6 + seg];
            *(uint4*)&As[row * AS_LD + seg * 8] = v;
        }
        // load B tile 48x80 halfs: 480 uint4, threads 0..159 x3
        if (tid < 160) {
#pragma unroll
            for (int j = 0; j < 3; j++) {
                int i = tid + 160 * j;
                int row = i / 10, seg = i - row * 10;
                uint4 v = Bp[(size_t)(kt * 48 + row) * BSTRIDE
                             + blockIdx.y * 10 + seg];
                *(uint4*)&Bs[row * BS_LD + seg * 8] = v;
            }
        }
        __syncthreads();

#pragma unroll
        for (int ks = 0; ks < 3; ks++) {
            unsigned afrag[2][4];
#pragma unroll
            for (int mt = 0; mt < 2; mt++) {
                int row = wm * 32 + mt * 16 + a_row_off;
                ldsm_x4(afrag[mt],
                        as_base + (unsigned)((row * AS_LD + ks * 16 + a_k_sub) * 2));
            }
#pragma unroll
            for (int nt = 0; nt < 5; nt++) {
                unsigned bfrag[2];
                int ncol = wn * 40 + nt * 8;
                ldsm_x2t(bfrag,
                         bs_base + (unsigned)(((ks * 16 + lane16) * BS_LD + ncol) * 2));
#pragma unroll
                for (int mt = 0; mt < 2; mt++)
                    mma16816(acc[mt][nt], afrag[mt], bfrag);
            }
        }
        __syncthreads();
    }

#pragma unroll
    for (int mt = 0; mt < 2; mt++) {
#pragma unroll
        for (int nt = 0; nt < 5; nt++) {
            int r0  = m0 + wm * 32 + mt * 16 + (lane >> 2);
            int col = n0 + wn * 40 + nt * 8 + (lane & 3) * 2;
            if (DST == 0) {
                if (r0 < M) {
                    __half2 h = __floats2half2_rn(acc[mt][nt][0], acc[mt][nt][1]);
                    *(__half2*)&g_bufH[(size_t)r0 * F_HID + col] = h;
                }
                int r1 = r0 + 8;
                if (r1 < M) {
                    __half2 h = __floats2half2_rn(acc[mt][nt][2], acc[mt][nt][3]);
                    *(__half2*)&g_bufH[(size_t)r1 * F_HID + col] = h;
                }
            } else {
                float bx = bias[col], by = bias[col + 1];
                if (r0 < M) {
                    float2 o = make_float2(acc[mt][nt][0] + bx, acc[mt][nt][1] + by);
                    *(float2*)&Cout[(size_t)r0 * F_OUT + col] = o;
                }
                int r1 = r0 + 8;
                if (r1 < M) {
                    float2 o = make_float2(acc[mt][nt][2] + bx, acc[mt][nt][3] + by);
                    *(float2*)&Cout[(size_t)r1 * F_OUT + col] = o;
                }
            }
        }
    }
}

// ---------------- launch ----------------------------------------------------
// Dataflow:
//   gemm1:        x @ W1                  -> bufH (fp16)
//   agg :         relu(max-agg(bufH)+b1)  -> aggH (fp16)
//   gemm_mma<0>:  aggH @ W2h (HMMA)       -> bufH (fp16)
//   agg :         relu(max-agg(bufH)+b2)  -> aggH (fp16)
//   gemm_mma<1>:  aggH @ Weh + be (HMMA)  -> out  (fp32)
extern "C" void kernel_launch(void* const* d_in, const int* in_sizes, int n_in,
                              void* d_out, int out_size) {
    const float* x  = (const float*)d_in[0];
    const int*   ei = (const int*)d_in[1];     // int32 (JAX x64 disabled)
    const float* ew = (const float*)d_in[2];
    const float* W1 = (const float*)d_in[3];
    const float* b1 = (const float*)d_in[4];
    const float* W2 = (const float*)d_in[5];
    const float* b2 = (const float*)d_in[6];
    const float* We = (const float*)d_in[7];
    const float* be = (const float*)d_in[8];
    float* out = (float*)d_out;

    const int TB = 256;
    int gN = (N_NODES + TB - 1) / TB;
    int gE = (N_EDGES + TB - 1) / TB;

    // graph structure (shared by both layers)
    zero_kernel<<<gN, TB>>>();
    deg_kernel<<<gE, TB>>>(ei, ew);
    scan_kernel<<<SCAN_G, SCAN_B>>>();          // lookback scan + dis + cnt
    fill_kernel<<<gE, TB>>>(ei, ew);
    cvtW_kernel<<<(F_HID * F_HID / 4 + F_HID * F_OUT / 4 + TB - 1) / TB, TB>>>(W2, We);

    // layer 1
    gemm1_kernel<<<(N_NODES * 60 + TB - 1) / TB, TB>>>(x, W1);
    agg_kernel<<<(N_NODES + 7) / 8, 256>>>(b1);

    // layer 2 (tensor cores)
    {
        dim3 grid((N_NODES + 127) / 128, F_HID / 80);
        gemm_mma_kernel<0><<<grid, 256>>>(nullptr, nullptr, N_NODES);
    }
    agg_kernel<<<(N_NODES + 7) / 8, 256>>>(b2);

    // head (tensor cores, fp32 out)
    {
        dim3 grid((N_NODES + 127) / 128, 1);
        gemm_mma_kernel<1><<<grid, 256>>>(be, out, N_NODES);
    }
}